// round 6
// baseline (speedup 1.0000x reference)
#include <cuda_runtime.h>
#include <cuda_bf16.h>
#include <math.h>
#include <stdint.h>

#define S_ 1024
#define B_ 8
#define D_ 1024
#define H_ 16
#define F_ 4096
#define M_TOK (S_*B_)   // 8192

// ---------------- scratch (device globals; no allocation) ----------------
__device__ float g_Q [8388608];      // Q projection f32 (tf32-rounded)
__device__ float g_K [8388608];      // K projection f32 (natural layout)
__device__ float g_V [8388608];      // V projection f32
__device__ float g_ao[8388608];      // attn out-projection
__device__ float g_x [8388608];      // LN1 output f32
__device__ float g_f2[8388608];      // FFN output
__device__ float g_attn_fb[134217728]; // raw scores / probs fallback

__device__ __nv_bfloat16 g_qk_h [8388608],  g_qk_l [8388608];
__device__ __nv_bfloat16 g_src_h[8388608],  g_src_l[8388608];
__device__ __nv_bfloat16 g_x_h  [8388608],  g_x_l  [8388608];
__device__ __nv_bfloat16 g_ctx_h[8388608],  g_ctx_l[8388608];
__device__ __nv_bfloat16 g_h1_h [33554432], g_h1_l [33554432];
__device__ __nv_bfloat16 g_w_h  [12582912], g_w_l  [12582912];

// ---------------- helpers ----------------
__device__ __forceinline__ float tf32r(float v) {
    unsigned r; asm("cvt.rna.tf32.f32 %0, %1;" : "=r"(r) : "f"(v));
    return __uint_as_float(r);
}
__device__ __forceinline__ void cp16(void* s, const void* g) {
    unsigned sa = (unsigned)__cvta_generic_to_shared(s);
    asm volatile("cp.async.ca.shared.global [%0], [%1], 16;" :: "r"(sa), "l"(g));
}
#define CP_COMMIT() asm volatile("cp.async.commit_group;")
#define CP_WAIT0()  asm volatile("cp.async.wait_group 0;")
#define CP_WAIT1()  asm volatile("cp.async.wait_group 1;")

__device__ __forceinline__ void mma_tf32(float* d, const unsigned* a, const unsigned* b) {
    asm volatile(
        "mma.sync.aligned.m16n8k8.row.col.f32.tf32.tf32.f32 "
        "{%0,%1,%2,%3}, {%4,%5,%6,%7}, {%8,%9}, {%0,%1,%2,%3};"
        : "+f"(d[0]), "+f"(d[1]), "+f"(d[2]), "+f"(d[3])
        : "r"(a[0]), "r"(a[1]), "r"(a[2]), "r"(a[3]), "r"(b[0]), "r"(b[1]));
}
__device__ __forceinline__ void mma_bf16(float* d, const unsigned* a, const unsigned* b) {
    asm volatile(
        "mma.sync.aligned.m16n8k16.row.col.f32.bf16.bf16.f32 "
        "{%0,%1,%2,%3}, {%4,%5,%6,%7}, {%8,%9}, {%0,%1,%2,%3};"
        : "+f"(d[0]), "+f"(d[1]), "+f"(d[2]), "+f"(d[3])
        : "r"(a[0]), "r"(a[1]), "r"(a[2]), "r"(a[3]), "r"(b[0]), "r"(b[1]));
}
__device__ __forceinline__ void ldm4(uint32_t* r, uint32_t saddr) {
    asm volatile("ldmatrix.sync.aligned.m8n8.x4.shared.b16 {%0,%1,%2,%3}, [%4];"
        : "=r"(r[0]), "=r"(r[1]), "=r"(r[2]), "=r"(r[3]) : "r"(saddr));
}
__device__ __forceinline__ uint32_t smem_u32(const void* p) {
    return (uint32_t)__cvta_generic_to_shared(p);
}
__device__ __forceinline__ uint32_t pack_bf16(float a, float b) {
    __nv_bfloat162 t;
    t.x = __float2bfloat16(a); t.y = __float2bfloat16(b);
    return *(uint32_t*)&t;
}
__device__ __forceinline__ uint32_t pack_bf16_lo(float a, float b) {
    float ha = __bfloat162float(__float2bfloat16(a));
    float hb = __bfloat162float(__float2bfloat16(b));
    return pack_bf16(a - ha, b - hb);
}

// ================== split-bf16 GEMM via ldmatrix (linear layers) ==================
// C[M,N] = A[M,K] @ B[N,K]^T + bias.  A,B given as bf16 hi/lo (K-major rows).
// 3-term split: Ah*Bh + Al*Bh + Ah*Bl (error ~2^-16).
// Tile 128x128, BK=32, 256 threads (8 warps: wm=wid&3, wn=wid>>2), double-buffered.
__global__ void __launch_bounds__(256, 2) bf_gemm(
    const __nv_bfloat16* __restrict__ Ahp, const __nv_bfloat16* __restrict__ Alp,
    const __nv_bfloat16* __restrict__ Bhp, const __nv_bfloat16* __restrict__ Blp,
    const float* __restrict__ bias,
    float* __restrict__ Cf, __nv_bfloat16* __restrict__ Ch, __nv_bfloat16* __restrict__ Cl,
    int K, int relu, int rnd, int splitout)
{
    extern __shared__ char smem[];
    const uint32_t su = smem_u32(smem);
    const int tid = threadIdx.x;
    const int wid = tid >> 5, lane = tid & 31;
    const int wm = wid & 3, wn = wid >> 2;
    const int qr = lane >> 2, qc = lane & 3;
    const int m0 = blockIdx.y * 128;
    const int n0 = blockIdx.x * 128;
    const int ldc = gridDim.x * 128;

    // stage: 40960 B = Ah(10240) | Al | Bh | Bl, each 128 rows x 80 B (32 bf16 + pad)
    auto ld_stage = [&](int st, int k0) {
        const int sb = st * 40960;
        const __nv_bfloat16* gp[4] = {Ahp, Alp, Bhp, Blp};
        #pragma unroll
        for (int p = 0; p < 4; p++) {
            const __nv_bfloat16* G = gp[p] + (size_t)((p < 2) ? m0 : n0) * K + k0;
            #pragma unroll
            for (int i = 0; i < 2; i++) {
                int c = tid + i * 256;
                int r = c >> 2, ch = c & 3;
                cp16(smem + sb + p * 10240 + r * 80 + ch * 16,
                     G + (size_t)r * K + ch * 8);
            }
        }
    };

    float acc[2][8][4];
    #pragma unroll
    for (int mi = 0; mi < 2; mi++)
        #pragma unroll
        for (int ni = 0; ni < 8; ni++)
            #pragma unroll
            for (int j = 0; j < 4; j++) acc[mi][ni][j] = 0.0f;

    const int nk = K >> 5;
    ld_stage(0, 0);
    CP_COMMIT();

    for (int kt = 0; kt < nk; kt++) {
        if (kt + 1 < nk) {
            ld_stage((kt + 1) & 1, (kt + 1) << 5);
            CP_COMMIT();
            CP_WAIT1();
        } else {
            CP_WAIT0();
        }
        __syncthreads();

        const uint32_t sb = su + (kt & 1) * 40960;
        #pragma unroll
        for (int k16 = 0; k16 < 2; k16++) {
            uint32_t ah[2][4], al[2][4];
            #pragma unroll
            for (int mi = 0; mi < 2; mi++) {
                int row = wm * 32 + mi * 16 + (lane & 15);
                int bofs = row * 80 + k16 * 32 + ((lane >> 4) << 4);
                ldm4(ah[mi], sb + bofs);
                ldm4(al[mi], sb + 10240 + bofs);
            }
            #pragma unroll
            for (int p = 0; p < 4; p++) {
                uint32_t bhf[4], blf[4];
                int nrow = wn * 64 + p * 16 + (lane & 7) + ((lane >> 4) << 3);
                int bofs = nrow * 80 + k16 * 32 + (((lane >> 3) & 1) << 4);
                ldm4(bhf, sb + 20480 + bofs);
                ldm4(blf, sb + 30720 + bofs);
                #pragma unroll
                for (int mi = 0; mi < 2; mi++) {
                    mma_bf16(acc[mi][2 * p + 0], ah[mi], bhf);
                    mma_bf16(acc[mi][2 * p + 0], al[mi], bhf);
                    mma_bf16(acc[mi][2 * p + 0], ah[mi], blf);
                    mma_bf16(acc[mi][2 * p + 1], ah[mi], bhf + 2);
                    mma_bf16(acc[mi][2 * p + 1], al[mi], bhf + 2);
                    mma_bf16(acc[mi][2 * p + 1], ah[mi], blf + 2);
                }
            }
        }
        __syncthreads();
    }

    // epilogue
    #pragma unroll
    for (int mi = 0; mi < 2; mi++) {
        #pragma unroll
        for (int ni = 0; ni < 8; ni++) {
            int rbase = m0 + wm * 32 + mi * 16 + qr;
            int cc = n0 + wn * 64 + ni * 8 + (qc << 1);
            float b0 = bias[cc], b1 = bias[cc + 1];
            #pragma unroll
            for (int h2 = 0; h2 < 2; h2++) {
                int row = rbase + h2 * 8;
                float v0 = acc[mi][ni][h2 * 2 + 0] + b0;
                float v1 = acc[mi][ni][h2 * 2 + 1] + b1;
                if (relu) { v0 = fmaxf(v0, 0.0f); v1 = fmaxf(v1, 0.0f); }
                size_t o = (size_t)row * ldc + cc;
                if (splitout) {
                    *(uint32_t*)&Ch[o] = pack_bf16(v0, v1);
                    *(uint32_t*)&Cl[o] = pack_bf16_lo(v0, v1);
                } else {
                    if (rnd) { v0 = tf32r(v0); v1 = tf32r(v1); }
                    *(float2*)(Cf + o) = make_float2(v0, v1);
                }
            }
        }
    }
}

// ================== tf32 fragment GEMM (scores only) ==================
// C = alpha * A @ B^T per (b,h); B given in natural K-major layout [n][k] (bkmaj).
__global__ void __launch_bounds__(256, 2) mma_gemm(
    const float* __restrict__ A, const float* __restrict__ W,
    float* __restrict__ C, int K, int lda, int ldb, int ldc, int zdiv,
    long long sAh, long long sAl, long long sBh, long long sBl,
    long long sCh, long long sCl, float alpha)
{
    constexpr int AS_SZ = 128 * 36;

    extern __shared__ float fsm[];
    float* As0 = fsm;
    float* Ws0 = fsm + 2 * AS_SZ;

    int tid = threadIdx.x;
    int wid = tid >> 5, lane = tid & 31;
    int wm = wid & 3, wn = wid >> 2;
    int m0 = blockIdx.y * 128;
    int n0 = blockIdx.x * 128;
    int z  = blockIdx.z;

    const float* Ag = A + (long long)(z / zdiv) * sAh + (long long)(z % zdiv) * sAl
                        + (size_t)m0 * lda;
    const float* Wg = W + (long long)(z / zdiv) * sBh + (long long)(z % zdiv) * sBl
                        + (size_t)n0 * ldb;
    float* Cg = C + (long long)(z / zdiv) * sCh + (long long)(z % zdiv) * sCl;

    float acc[2][8][4];
    #pragma unroll
    for (int mi = 0; mi < 2; mi++)
        #pragma unroll
        for (int ni = 0; ni < 8; ni++)
            #pragma unroll
            for (int j = 0; j < 4; j++) acc[mi][ni][j] = 0.0f;

    auto load_stage = [&](int buf, int k0) {
        float* as = As0 + buf * AS_SZ;
        float* ws = Ws0 + buf * AS_SZ;
        #pragma unroll
        for (int i = 0; i < 4; i++) {           // A: 128 rows x 32 k
            int c = tid + i * 256;
            int r = c >> 3, c4 = (c & 7) * 4;
            cp16(&as[r * 36 + c4], Ag + (size_t)r * lda + k0 + c4);
        }
        #pragma unroll
        for (int i = 0; i < 4; i++) {           // B: 128 n-rows x 32 k
            int c = tid + i * 256;
            int r = c >> 3, c4 = (c & 7) * 4;
            cp16(&ws[r * 36 + c4], Wg + (size_t)r * ldb + k0 + c4);
        }
    };

    int nk = K >> 5;
    load_stage(0, 0);
    CP_COMMIT();

    for (int kt = 0; kt < nk; kt++) {
        if (kt + 1 < nk) {
            load_stage((kt + 1) & 1, (kt + 1) << 5);
            CP_COMMIT();
            CP_WAIT1();
        } else {
            CP_WAIT0();
        }
        __syncthreads();

        const float* as = As0 + (kt & 1) * AS_SZ;
        const float* ws = Ws0 + (kt & 1) * AS_SZ;
        #pragma unroll
        for (int kk = 0; kk < 32; kk += 8) {
            unsigned afr[2][4];
            #pragma unroll
            for (int mi = 0; mi < 2; mi++) {
                int r = wm * 32 + mi * 16 + (lane >> 2);
                int c = kk + (lane & 3);
                afr[mi][0] = __float_as_uint(as[r * 36 + c]);
                afr[mi][1] = __float_as_uint(as[(r + 8) * 36 + c]);
                afr[mi][2] = __float_as_uint(as[r * 36 + c + 4]);
                afr[mi][3] = __float_as_uint(as[(r + 8) * 36 + c + 4]);
            }
            #pragma unroll
            for (int ni = 0; ni < 8; ni++) {
                int n = wn * 64 + ni * 8 + (lane >> 2);
                unsigned bfr[2];
                bfr[0] = __float_as_uint(ws[n * 36 + kk + (lane & 3)]);
                bfr[1] = __float_as_uint(ws[n * 36 + kk + (lane & 3) + 4]);
                #pragma unroll
                for (int mi = 0; mi < 2; mi++)
                    mma_tf32(acc[mi][ni], afr[mi], bfr);
            }
        }
        __syncthreads();
    }

    #pragma unroll
    for (int mi = 0; mi < 2; mi++) {
        #pragma unroll
        for (int ni = 0; ni < 8; ni++) {
            int rbase = m0 + wm * 32 + mi * 16 + (lane >> 2);
            int cc = n0 + wn * 64 + ni * 8 + (lane & 3) * 2;
            #pragma unroll
            for (int h2 = 0; h2 < 2; h2++) {
                int row = rbase + h2 * 8;
                float v0 = acc[mi][ni][h2 * 2 + 0] * alpha;
                float v1 = acc[mi][ni][h2 * 2 + 1] * alpha;
                *(float2*)(Cg + (size_t)row * ldc + cc) = make_float2(v0, v1);
            }
        }
    }
}

// ================== fused softmax + AV GEMM ==================
// One CTA: 128 P-rows x DK=64 for one (b,h); ctx written as bf16 hi/lo splits.
__global__ void __launch_bounds__(256, 2) av_softmax(
    const float* __restrict__ sc, const float* __restrict__ V,
    float* __restrict__ probs,
    __nv_bfloat16* __restrict__ ctxh, __nv_bfloat16* __restrict__ ctxl)
{
    extern __shared__ char sm[];
    float* as = (float*)sm;                       // [128][68]
    float* vs = (float*)(sm + 34816);             // 2 x [64][68]
    float* rinv = (float*)(sm + 69632);           // [128]

    const int tid = threadIdx.x;
    const int w = tid >> 5, lane = tid & 31;
    const int wm = w & 3, wn = w >> 2;
    const int qr = lane >> 2, qc = lane & 3;
    const int bh = blockIdx.y, b = bh >> 4, h = bh & 15;
    const int m0 = blockIdx.x * 128;
    const float* scb = sc + ((size_t)bh << 20) + (size_t)m0 * 1024;
    float* prb = probs + ((size_t)bh << 20) + (size_t)m0 * 1024;

    {   // pass 1: row sums of exp (scores are O(1); no max subtraction needed)
        int row = tid >> 1, half = tid & 1;
        const float4* pr = (const float4*)(scb + (size_t)row * 1024 + half * 512);
        float s = 0.0f;
        #pragma unroll 4
        for (int i = 0; i < 128; i++) {
            float4 v = pr[i];
            s += __expf(v.x) + __expf(v.y) + __expf(v.z) + __expf(v.w);
        }
        s += __shfl_xor_sync(0xffffffffu, s, 1);
        if (half == 0) rinv[row] = 1.0f / s;
    }
    __syncthreads();

    auto ldV = [&](int kc) {
        float* dst = vs + (kc & 1) * (64 * 68);
        #pragma unroll
        for (int i = 0; i < 4; i++) {
            int idx = tid + i * 256;
            int r = idx >> 4, c4 = (idx & 15) << 2;
            cp16(&dst[r * 68 + c4],
                 &V[((size_t)(b * 1024 + kc * 64 + r)) * 1024 + h * 64 + c4]);
        }
    };

    float acc[2][4][4];
    #pragma unroll
    for (int mi = 0; mi < 2; mi++)
        #pragma unroll
        for (int ni = 0; ni < 4; ni++)
            #pragma unroll
            for (int j = 0; j < 4; j++) acc[mi][ni][j] = 0.0f;

    ldV(0);
    CP_COMMIT();

    for (int kc = 0; kc < 16; kc++) {
        #pragma unroll
        for (int i = 0; i < 8; i++) {
            int idx = tid + i * 256;
            int r = idx >> 4, c4 = (idx & 15) << 2;
            float inv = rinv[r];
            float4 x = *(const float4*)&scb[(size_t)r * 1024 + kc * 64 + c4];
            float4 p;
            p.x = __expf(x.x) * inv; p.y = __expf(x.y) * inv;
            p.z = __expf(x.z) * inv; p.w = __expf(x.w) * inv;
            *(float4*)&prb[(size_t)r * 1024 + kc * 64 + c4] = p;
            float4 q;
            q.x = tf32r(p.x); q.y = tf32r(p.y); q.z = tf32r(p.z); q.w = tf32r(p.w);
            *(float4*)&as[r * 68 + c4] = q;
        }
        if (kc + 1 < 16) {
            ldV(kc + 1);
            CP_COMMIT();
            CP_WAIT1();
        } else {
            CP_WAIT0();
        }
        __syncthreads();

        const float* vb = vs + (kc & 1) * (64 * 68);
        #pragma unroll
        for (int kk = 0; kk < 8; kk++) {
            unsigned a[2][4];
            #pragma unroll
            for (int mi = 0; mi < 2; mi++) {
                int r = wm * 32 + mi * 16 + qr;
                int c = kk * 8 + qc;
                a[mi][0] = __float_as_uint(as[r * 68 + c]);
                a[mi][1] = __float_as_uint(as[(r + 8) * 68 + c]);
                a[mi][2] = __float_as_uint(as[r * 68 + c + 4]);
                a[mi][3] = __float_as_uint(as[(r + 8) * 68 + c + 4]);
            }
            #pragma unroll
            for (int ni = 0; ni < 4; ni++) {
                int n = wn * 32 + ni * 8 + qr;
                unsigned bb[2];
                bb[0] = __float_as_uint(vb[(kk * 8 + qc) * 68 + n]);
                bb[1] = __float_as_uint(vb[(kk * 8 + qc + 4) * 68 + n]);
                #pragma unroll
                for (int mi = 0; mi < 2; mi++)
                    mma_tf32(acc[mi][ni], a[mi], bb);
            }
        }
        __syncthreads();
    }

    // epilogue -> ctx splits (bf16 hi/lo; feeds Wo GEMM)
    #pragma unroll
    for (int mi = 0; mi < 2; mi++) {
        #pragma unroll
        for (int ni = 0; ni < 4; ni++) {
            int r = m0 + wm * 32 + mi * 16 + qr;
            int c = h * 64 + wn * 32 + ni * 8 + (qc << 1);
            size_t o0 = ((size_t)(b * 1024 + r)) * 1024 + c;
            size_t o1 = ((size_t)(b * 1024 + r + 8)) * 1024 + c;
            *(uint32_t*)&ctxh[o0] = pack_bf16(acc[mi][ni][0], acc[mi][ni][1]);
            *(uint32_t*)&ctxl[o0] = pack_bf16_lo(acc[mi][ni][0], acc[mi][ni][1]);
            *(uint32_t*)&ctxh[o1] = pack_bf16(acc[mi][ni][2], acc[mi][ni][3]);
            *(uint32_t*)&ctxl[o1] = pack_bf16_lo(acc[mi][ni][2], acc[mi][ni][3]);
        }
    }
}

// ---------------- prep: [S,B,D] -> batch-first bf16 splits ----------------
__global__ void prep_kernel(const float* __restrict__ src, const float* __restrict__ pos,
                            __nv_bfloat16* __restrict__ qh, __nv_bfloat16* __restrict__ ql,
                            __nv_bfloat16* __restrict__ sh, __nv_bfloat16* __restrict__ sl)
{
    size_t idx = (size_t)blockIdx.x * blockDim.x + threadIdx.x;
    if (idx >= (size_t)S_ * B_ * D_) return;
    int d = (int)(idx % D_);
    size_t sb = idx / D_;
    int b = (int)(sb % B_);
    int s = (int)(sb / B_);
    size_t o = ((size_t)(b * S_ + s)) * D_ + d;
    float sv = src[idx];
    float qv = sv + pos[idx];
    __nv_bfloat16 qhi = __float2bfloat16(qv);
    __nv_bfloat16 shi = __float2bfloat16(sv);
    qh[o] = qhi; ql[o] = __float2bfloat16(qv - __bfloat162float(qhi));
    sh[o] = shi; sl[o] = __float2bfloat16(sv - __bfloat162float(shi));
}

// ---------------- weight transpose + split: W[K,N] -> T[N,K] hi/lo ----------
__global__ void wsplit_kernel(const float* __restrict__ W,
                              __nv_bfloat16* __restrict__ Th, __nv_bfloat16* __restrict__ Tl,
                              int K, int N)
{
    __shared__ float t[32][33];
    int n0 = blockIdx.x * 32, k0 = blockIdx.y * 32;
    int tx = threadIdx.x, ty = threadIdx.y;
    #pragma unroll
    for (int i = 0; i < 32; i += 8)
        t[ty + i][tx] = W[(size_t)(k0 + ty + i) * N + n0 + tx];
    __syncthreads();
    #pragma unroll
    for (int i = 0; i < 32; i += 8) {
        float v = t[tx][ty + i];
        __nv_bfloat16 h = __float2bfloat16(v);
        size_t o = (size_t)(n0 + ty + i) * K + k0 + tx;
        Th[o] = h;
        Tl[o] = __float2bfloat16(v - __bfloat162float(h));
    }
}

// ---------------- fused add + LayerNorm (+ optional bf16 split out) --------
__global__ void ln_kernel(const float* __restrict__ in1, int in1_sbd,
                          const float* __restrict__ in2,
                          const float* __restrict__ gamma, const float* __restrict__ beta,
                          float* __restrict__ out, int out_sbd,
                          __nv_bfloat16* __restrict__ oh, __nv_bfloat16* __restrict__ ol)
{
    int m = blockIdx.x;
    int b = m / S_, s = m % S_;
    size_t sbd_off = ((size_t)(s * B_ + b)) * D_;
    size_t bf_off  = (size_t)m * D_;
    const float* p1 = in1 + (in1_sbd ? sbd_off : bf_off);
    const float* p2 = in2 + bf_off;
    float* po = out + (out_sbd ? sbd_off : bf_off);

    __shared__ float xs[D_];
    __shared__ float r1[256], r2[256];
    int tid = threadIdx.x;
    float s1 = 0.0f, s2 = 0.0f;
    for (int d = tid; d < D_; d += 256) {
        float v = p1[d] + p2[d];
        xs[d] = v; s1 += v; s2 += v * v;
    }
    r1[tid] = s1; r2[tid] = s2;
    __syncthreads();
    for (int st = 128; st > 0; st >>= 1) {
        if (tid < st) { r1[tid] += r1[tid + st]; r2[tid] += r2[tid + st]; }
        __syncthreads();
    }
    float mean = r1[0] * (1.0f / D_);
    float var  = r2[0] * (1.0f / D_) - mean * mean;
    float rstd = rsqrtf(var + 1e-5f);
    for (int d = tid; d < D_; d += 256) {
        float v = (xs[d] - mean) * rstd * gamma[d] + beta[d];
        po[d] = v;
        if (oh) {
            __nv_bfloat16 h = __float2bfloat16(v);
            oh[bf_off + d] = h;
            ol[bf_off + d] = __float2bfloat16(v - __bfloat162float(h));
        }
    }
}

// ---------------- launch ----------------
extern "C" void kernel_launch(void* const* d_in, const int* in_sizes, int n_in,
                              void* d_out, int out_size)
{
    static float *Qb = nullptr, *Kb, *Vb, *ao, *x, *f2, *attn_fb;
    static __nv_bfloat16 *qk_h, *qk_l, *src_h, *src_l, *x_h, *x_l,
                         *ctx_h, *ctx_l, *h1_h, *h1_l, *w_h, *w_l;
    if (!Qb) {
        cudaGetSymbolAddress((void**)&Qb,    g_Q);
        cudaGetSymbolAddress((void**)&Kb,    g_K);
        cudaGetSymbolAddress((void**)&Vb,    g_V);
        cudaGetSymbolAddress((void**)&ao,    g_ao);
        cudaGetSymbolAddress((void**)&x,     g_x);
        cudaGetSymbolAddress((void**)&f2,    g_f2);
        cudaGetSymbolAddress((void**)&attn_fb, g_attn_fb);
        cudaGetSymbolAddress((void**)&qk_h,  g_qk_h);
        cudaGetSymbolAddress((void**)&qk_l,  g_qk_l);
        cudaGetSymbolAddress((void**)&src_h, g_src_h);
        cudaGetSymbolAddress((void**)&src_l, g_src_l);
        cudaGetSymbolAddress((void**)&x_h,   g_x_h);
        cudaGetSymbolAddress((void**)&x_l,   g_x_l);
        cudaGetSymbolAddress((void**)&ctx_h, g_ctx_h);
        cudaGetSymbolAddress((void**)&ctx_l, g_ctx_l);
        cudaGetSymbolAddress((void**)&h1_h,  g_h1_h);
        cudaGetSymbolAddress((void**)&h1_l,  g_h1_l);
        cudaGetSymbolAddress((void**)&w_h,   g_w_h);
        cudaGetSymbolAddress((void**)&w_l,   g_w_l);
    }

    const float* src = (const float*)d_in[0];
    const float* pos = (const float*)d_in[1];
    const float* Wq  = (const float*)d_in[2];
    const float* bq  = (const float*)d_in[3];
    const float* Wk  = (const float*)d_in[4];
    const float* bk  = (const float*)d_in[5];
    const float* Wv  = (const float*)d_in[6];
    const float* bv  = (const float*)d_in[7];
    const float* Wo  = (const float*)d_in[8];
    const float* bo  = (const float*)d_in[9];
    const float* W1  = (const float*)d_in[10];
    const float* b1  = (const float*)d_in[11];
    const float* W2  = (const float*)d_in[12];
    const float* b2  = (const float*)d_in[13];
    const float* g1  = (const float*)d_in[14];
    const float* be1 = (const float*)d_in[15];
    const float* g2  = (const float*)d_in[16];
    const float* be2 = (const float*)d_in[17];

    float* out = (float*)d_out;
    long long need = (long long)S_ * B_ * D_ + (long long)B_ * H_ * S_ * S_;
    float* scores = attn_fb;
    float* probs  = ((long long)out_size >= need) ? out + (size_t)S_ * B_ * D_ : attn_fb;

    const int SMB = 2 * 40960;                    // bf_gemm: 81920 B
    const int SMG = (2 * 4608 + 2 * 4608) * 4;    // tf32 scores: 73728 B
    const int SMA = 70144;                        // av_softmax
    cudaFuncSetAttribute(bf_gemm,    cudaFuncAttributeMaxDynamicSharedMemorySize, SMB);
    cudaFuncSetAttribute(mma_gemm,   cudaFuncAttributeMaxDynamicSharedMemorySize, SMG);
    cudaFuncSetAttribute(av_softmax, cudaFuncAttributeMaxDynamicSharedMemorySize, SMA);

    __nv_bfloat16* wq_h = w_h;             __nv_bfloat16* wq_l = w_l;
    __nv_bfloat16* wk_h = w_h + 1048576;   __nv_bfloat16* wk_l = w_l + 1048576;
    __nv_bfloat16* wv_h = w_h + 2097152;   __nv_bfloat16* wv_l = w_l + 2097152;
    __nv_bfloat16* wo_h = w_h + 3145728;   __nv_bfloat16* wo_l = w_l + 3145728;
    __nv_bfloat16* w1_h = w_h + 4194304;   __nv_bfloat16* w1_l = w_l + 4194304;
    __nv_bfloat16* w2_h = w_h + 8388608;   __nv_bfloat16* w2_l = w_l + 8388608;

    // 1) prep: weight transpose+split; input splits
    dim3 wb(32, 8);
    wsplit_kernel<<<dim3(32, 32), wb>>>(Wq, wq_h, wq_l, 1024, 1024);
    wsplit_kernel<<<dim3(32, 32), wb>>>(Wk, wk_h, wk_l, 1024, 1024);
    wsplit_kernel<<<dim3(32, 32), wb>>>(Wv, wv_h, wv_l, 1024, 1024);
    wsplit_kernel<<<dim3(32, 32), wb>>>(Wo, wo_h, wo_l, 1024, 1024);
    wsplit_kernel<<<dim3(128, 32), wb>>>(W1, w1_h, w1_l, 1024, 4096);
    wsplit_kernel<<<dim3(32, 128), wb>>>(W2, w2_h, w2_l, 4096, 1024);
    prep_kernel<<<(unsigned)(((size_t)S_ * B_ * D_ + 255) / 256), 256>>>(
        src, pos, qk_h, qk_l, src_h, src_l);

    const long long SD = (long long)S_ * D_;
    const long long SS = (long long)S_ * S_;

    // 2-4) QKV projections (split-bf16); outputs f32 tf32-rounded
    bf_gemm<<<dim3(8, 64), 256, SMB>>>(qk_h, qk_l, wq_h, wq_l, bq,
        Qb, nullptr, nullptr, 1024, 0, 1, 0);
    bf_gemm<<<dim3(8, 64), 256, SMB>>>(qk_h, qk_l, wk_h, wk_l, bk,
        Kb, nullptr, nullptr, 1024, 0, 1, 0);
    bf_gemm<<<dim3(8, 64), 256, SMB>>>(src_h, src_l, wv_h, wv_l, bv,
        Vb, nullptr, nullptr, 1024, 0, 1, 0);

    // 5) scores = Q @ K^T / 8  (tf32, natural K layout; per (b,h) M=N=1024 K=64)
    mma_gemm<<<dim3(8, 8, B_ * H_), 256, SMG>>>(Qb, Kb, scores,
        64, D_, D_, S_, H_,
        SD, 64, SD, 64, (long long)H_ * SS, SS, 0.125f);

    // 6) fused softmax + probs write + AV -> ctx splits
    av_softmax<<<dim3(8, B_ * H_), 256, SMA>>>(scores, Vb, probs, ctx_h, ctx_l);

    // 7) output projection
    bf_gemm<<<dim3(8, 64), 256, SMB>>>(ctx_h, ctx_l, wo_h, wo_l, bo,
        ao, nullptr, nullptr, 1024, 0, 0, 0);

    // 8) LN1: x = LN(src + ao) + splits for FFN
    ln_kernel<<<M_TOK, 256>>>(src, 1, ao, g1, be1, x, 0, x_h, x_l);

    // 9-10) FFN
    bf_gemm<<<dim3(32, 64), 256, SMB>>>(x_h, x_l, w1_h, w1_l, b1,
        nullptr, h1_h, h1_l, 1024, 1, 0, 1);
    bf_gemm<<<dim3(8, 64), 256, SMB>>>(h1_h, h1_l, w2_h, w2_l, b2,
        f2, nullptr, nullptr, 4096, 0, 0, 0);

    // 11) LN2 -> out in [S,B,D]
    ln_kernel<<<M_TOK, 256>>>(x, 0, f2, g2, be2, out, 1, nullptr, nullptr);
}

// round 8
// speedup vs baseline: 1.2409x; 1.2409x over previous
#include <cuda_runtime.h>
#include <math.h>
#include <stdint.h>

#define S_ 1024
#define B_ 8
#define D_ 1024
#define H_ 16
#define F_ 4096
#define M_TOK (S_*B_)

// ---------------- scratch ----------------
__device__ float g_qkin[8388608];    // perm src+pos
__device__ float g_srcbf[8388608];   // perm src
__device__ float g_Q [8388608];      // Q perm (reused as xp later)
__device__ float g_K [8388608];      // K perm
__device__ float g_V [8388608];      // V natural
__device__ float g_ctx[8388608];     // ctx perm
__device__ float g_ao[8388608];
__device__ float g_x [8388608];      // LN1 natural
__device__ float g_h1[33554432];     // h1 perm
__device__ float g_f2[8388608];
__device__ float g_wr[12582912];     // W^T perm [n][k]
__device__ float g_attn_fb[134217728];

// position j holds original element sigf(j); invf = sigf^-1
__device__ __forceinline__ int sigf(int j) { return ((j & 1) << 2) + (j >> 1); }
__device__ __forceinline__ int invf(int p) { return ((p & 3) << 1) + (p >> 2); }

__device__ __forceinline__ float tf32r(float v) {
    unsigned r; asm("cvt.rna.tf32.f32 %0, %1;" : "=r"(r) : "f"(v));
    return __uint_as_float(r);
}
__device__ __forceinline__ void cp16(void* s, const void* g) {
    unsigned sa = (unsigned)__cvta_generic_to_shared(s);
    asm volatile("cp.async.ca.shared.global [%0], [%1], 16;" :: "r"(sa), "l"(g));
}
#define CP_COMMIT() asm volatile("cp.async.commit_group;")
#define CP_WAIT0()  asm volatile("cp.async.wait_group 0;")
#define CP_WAIT1()  asm volatile("cp.async.wait_group 1;")

__device__ __forceinline__ void mma_tf32(float* d, const unsigned* a, const unsigned* b) {
    asm volatile(
        "mma.sync.aligned.m16n8k8.row.col.f32.tf32.tf32.f32 "
        "{%0,%1,%2,%3}, {%4,%5,%6,%7}, {%8,%9}, {%0,%1,%2,%3};"
        : "+f"(d[0]), "+f"(d[1]), "+f"(d[2]), "+f"(d[3])
        : "r"(a[0]), "r"(a[1]), "r"(a[2]), "r"(a[3]), "r"(b[0]), "r"(b[1]));
}

// ================== tf32 GEMM: 128x128 CTA tile, 4 warps (64x64 each) ==================
// A[m][k], B[n][k] k-contiguous, both k sigma-permuted per 8-group (so the tf32
// fragment pair (k, k+4) sits at adjacent stored positions -> LDS.64).
// 2-stage cp.async (R5-proven pattern), padded stride-40 smem rows, no swizzle.
__global__ void __launch_bounds__(128, 2) tgemm(
    const float* __restrict__ A, const float* __restrict__ Bm,
    const float* __restrict__ bias, float* __restrict__ C,
    int K, int lda, int ldb, int ldc, int zdiv,
    long long sAh, long long sAl, long long sBh, long long sBl,
    long long sCh, long long sCl,
    float alpha, int relu, int rnd, int permout)
{
    extern __shared__ float smem[];      // 2 stages x (A 5120 + B 5120 floats)
    const int tid = threadIdx.x;
    const int wid = tid >> 5, lane = tid & 31;
    const int wm = wid & 1, wn = wid >> 1;
    const int qr = lane >> 2, qc = lane & 3;
    const int m0 = blockIdx.y * 128;
    const int n0 = blockIdx.x * 128;
    const int z  = blockIdx.z;

    const float* Ag = A + (long long)(z / zdiv) * sAh + (long long)(z % zdiv) * sAl
                        + (size_t)m0 * lda;
    const float* Bg = Bm + (long long)(z / zdiv) * sBh + (long long)(z % zdiv) * sBl
                        + (size_t)n0 * ldb;
    float* Cg = C + (long long)(z / zdiv) * sCh + (long long)(z % zdiv) * sCl;

    auto ld_stage = [&](int s, int k0) {
        float* as = smem + s * 10240;
        float* bs = as + 5120;
        #pragma unroll
        for (int i = 0; i < 8; i++) {
            int idx = tid + i * 128;            // 1024 chunk slots: 128 rows x 8 chunks
            int r = idx >> 3, ch = idx & 7;
            cp16(&as[r * 40 + 4 * ch], Ag + (size_t)r * lda + k0 + 4 * ch);
            cp16(&bs[r * 40 + 4 * ch], Bg + (size_t)r * ldb + k0 + 4 * ch);
        }
    };

    float acc[4][8][4];
    #pragma unroll
    for (int mi = 0; mi < 4; mi++)
        #pragma unroll
        for (int ni = 0; ni < 8; ni++)
            #pragma unroll
            for (int j = 0; j < 4; j++) acc[mi][ni][j] = 0.0f;

    const int nk = K >> 5;
    ld_stage(0, 0);
    CP_COMMIT();

    for (int kt = 0; kt < nk; kt++) {
        if (kt + 1 < nk) {
            ld_stage((kt + 1) & 1, (kt + 1) << 5);
            CP_COMMIT();
            CP_WAIT1();
        } else {
            CP_WAIT0();
        }
        __syncthreads();
        const float* as = smem + (kt & 1) * 10240;
        const float* bs = as + 5120;

        #pragma unroll
        for (int kk = 0; kk < 4; kk++) {
            const int kx = (kk << 3) + (qc << 1);   // perm positions (2qc,2qc+1) = orig (qc,qc+4)
            float2 fa[4][2];
            float2 fb[8];
            #pragma unroll
            for (int mi = 0; mi < 4; mi++) {
                int r = wm * 64 + mi * 16 + qr;
                fa[mi][0] = *(const float2*)&as[r * 40 + kx];
                fa[mi][1] = *(const float2*)&as[(r + 8) * 40 + kx];
            }
            #pragma unroll
            for (int ni = 0; ni < 8; ni++) {
                int n = wn * 64 + ni * 8 + qr;
                fb[ni] = *(const float2*)&bs[n * 40 + kx];
            }
            #pragma unroll
            for (int mi = 0; mi < 4; mi++) {
                unsigned a[4];
                a[0] = __float_as_uint(fa[mi][0].x);
                a[1] = __float_as_uint(fa[mi][1].x);
                a[2] = __float_as_uint(fa[mi][0].y);
                a[3] = __float_as_uint(fa[mi][1].y);
                #pragma unroll
                for (int ni = 0; ni < 8; ni++) {
                    unsigned b[2];
                    b[0] = __float_as_uint(fb[ni].x);
                    b[1] = __float_as_uint(fb[ni].y);
                    mma_tf32(acc[mi][ni], a, b);
                }
            }
        }
        __syncthreads();
    }

    // epilogue: thread owns cols (2qc, 2qc+1) of each n8 group
    const int p0 = ((qc & 1) << 2) + (qc >> 1);   // invf(2qc); invf(2qc+1) = p0+2
    #pragma unroll
    for (int mi = 0; mi < 4; mi++) {
        #pragma unroll
        for (int ni = 0; ni < 8; ni++) {
            int r0 = m0 + wm * 64 + mi * 16 + qr;
            int cg = n0 + wn * 64 + ni * 8;
            int c0 = cg + (qc << 1);
            float b0 = 0.0f, b1 = 0.0f;
            if (bias) { b0 = bias[c0]; b1 = bias[c0 + 1]; }
            #pragma unroll
            for (int h2 = 0; h2 < 2; h2++) {
                int row = r0 + h2 * 8;
                float v0 = fmaf(acc[mi][ni][h2 * 2 + 0], alpha, b0);
                float v1 = fmaf(acc[mi][ni][h2 * 2 + 1], alpha, b1);
                if (relu) { v0 = fmaxf(v0, 0.0f); v1 = fmaxf(v1, 0.0f); }
                if (rnd)  { v0 = tf32r(v0); v1 = tf32r(v1); }
                if (permout) {
                    Cg[(size_t)row * ldc + cg + p0]     = v0;
                    Cg[(size_t)row * ldc + cg + p0 + 2] = v1;
                } else {
                    *(float2*)(Cg + (size_t)row * ldc + c0) = make_float2(v0, v1);
                }
            }
        }
    }
}

// ================== fused softmax + AV GEMM (R5-proven + perm P/ctx) ==================
__global__ void __launch_bounds__(256, 2) av_softmax(
    const float* __restrict__ sc, const float* __restrict__ V,
    float* __restrict__ probs, float* __restrict__ ctx)
{
    extern __shared__ char sm[];
    float* as = (float*)sm;                       // [128][68] perm P slice
    float* vs = (float*)(sm + 34816);             // 2 x [64][68]
    float* rinv = (float*)(sm + 69632);           // [128]

    const int tid = threadIdx.x;
    const int w = tid >> 5, lane = tid & 31;
    const int wm = w & 3, wn = w >> 2;
    const int qr = lane >> 2, qc = lane & 3;
    const int bh = blockIdx.y, b = bh >> 4, h = bh & 15;
    const int m0 = blockIdx.x * 128;
    const float* scb = sc + ((size_t)bh << 20) + (size_t)m0 * 1024;
    float* prb = probs + ((size_t)bh << 20) + (size_t)m0 * 1024;

    {   // pass 1: row sums of exp
        int row = tid >> 1, half = tid & 1;
        const float4* pr = (const float4*)(scb + (size_t)row * 1024 + half * 512);
        float s = 0.0f;
        #pragma unroll 4
        for (int i = 0; i < 128; i++) {
            float4 v = pr[i];
            s += __expf(v.x) + __expf(v.y) + __expf(v.z) + __expf(v.w);
        }
        s += __shfl_xor_sync(0xffffffffu, s, 1);
        if (half == 0) rinv[row] = 1.0f / s;
    }
    __syncthreads();

    auto ldV = [&](int kc) {
        float* dst = vs + (kc & 1) * (64 * 68);
        #pragma unroll
        for (int i = 0; i < 4; i++) {
            int idx = tid + i * 256;
            int r = idx >> 4, c4 = (idx & 15) << 2;
            cp16(&dst[r * 68 + c4],
                 &V[((size_t)(b * 1024 + kc * 64 + r)) * 1024 + h * 64 + c4]);
        }
    };

    float acc[2][4][4];
    #pragma unroll
    for (int mi = 0; mi < 2; mi++)
        #pragma unroll
        for (int ni = 0; ni < 4; ni++)
            #pragma unroll
            for (int j = 0; j < 4; j++) acc[mi][ni][j] = 0.0f;

    ldV(0);
    CP_COMMIT();

    for (int kc = 0; kc < 16; kc++) {
        #pragma unroll
        for (int i = 0; i < 8; i++) {
            int idx = tid + i * 256;
            int r = idx >> 4, c4 = (idx & 15) << 2;
            float inv = rinv[r];
            float4 x = *(const float4*)&scb[(size_t)r * 1024 + kc * 64 + c4];
            float4 p;
            p.x = __expf(x.x) * inv; p.y = __expf(x.y) * inv;
            p.z = __expf(x.z) * inv; p.w = __expf(x.w) * inv;
            *(float4*)&prb[(size_t)r * 1024 + kc * 64 + c4] = p;
            // sigma-permuted smem store: orig elems c4..c4+3 -> positions invf
            int base = r * 68 + (c4 & ~7) + ((c4 & 7) ? 1 : 0);
            as[base + 0] = tf32r(p.x);
            as[base + 2] = tf32r(p.y);
            as[base + 4] = tf32r(p.z);
            as[base + 6] = tf32r(p.w);
        }
        if (kc + 1 < 16) { ldV(kc + 1); CP_COMMIT(); CP_WAIT1(); }
        else CP_WAIT0();
        __syncthreads();

        const float* vb = vs + (kc & 1) * (64 * 68);
        #pragma unroll
        for (int kk = 0; kk < 8; kk++) {
            unsigned a[2][4];
            int kx = kk * 8 + (qc << 1);
            #pragma unroll
            for (int mi = 0; mi < 2; mi++) {
                int r = wm * 32 + mi * 16 + qr;
                float2 f0 = *(const float2*)&as[r * 68 + kx];
                float2 f1 = *(const float2*)&as[(r + 8) * 68 + kx];
                a[mi][0] = __float_as_uint(f0.x);
                a[mi][1] = __float_as_uint(f1.x);
                a[mi][2] = __float_as_uint(f0.y);
                a[mi][3] = __float_as_uint(f1.y);
            }
            #pragma unroll
            for (int ni = 0; ni < 4; ni++) {
                int n = wn * 32 + ni * 8 + qr;
                unsigned bb[2];
                bb[0] = __float_as_uint(vb[(kk * 8 + qc) * 68 + n]);
                bb[1] = __float_as_uint(vb[(kk * 8 + qc + 4) * 68 + n]);
                #pragma unroll
                for (int mi = 0; mi < 2; mi++)
                    mma_tf32(acc[mi][ni], a[mi], bb);
            }
        }
        __syncthreads();
    }

    // epilogue -> ctx (perm within d 8-groups, tf32-rounded)
    const int p0 = ((qc & 1) << 2) + (qc >> 1);
    #pragma unroll
    for (int mi = 0; mi < 2; mi++) {
        #pragma unroll
        for (int ni = 0; ni < 4; ni++) {
            int r = m0 + wm * 32 + mi * 16 + qr;
            int cg = h * 64 + wn * 32 + ni * 8;
            size_t o0 = ((size_t)(b * 1024 + r)) * 1024 + cg;
            size_t o1 = ((size_t)(b * 1024 + r + 8)) * 1024 + cg;
            ctx[o0 + p0]     = tf32r(acc[mi][ni][0]);
            ctx[o0 + p0 + 2] = tf32r(acc[mi][ni][1]);
            ctx[o1 + p0]     = tf32r(acc[mi][ni][2]);
            ctx[o1 + p0 + 2] = tf32r(acc[mi][ni][3]);
        }
    }
}

// ---------------- prep: [S,B,D] -> batch-first perm (tf32-rounded) ----------
__global__ void prep_kernel(const float* __restrict__ src, const float* __restrict__ pos,
                            float* __restrict__ qkin, float* __restrict__ srcbf)
{
    size_t idx = (size_t)blockIdx.x * blockDim.x + threadIdx.x;
    if (idx >= (size_t)S_ * B_ * D_) return;
    int d = (int)(idx % D_);
    size_t sb = idx / D_;
    int b = (int)(sb % B_);
    int s = (int)(sb / B_);
    int dp = (d & ~7) + invf(d & 7);
    size_t o = ((size_t)(b * S_ + s)) * D_ + dp;
    float sv = src[idx];
    qkin[o]  = tf32r(sv + pos[idx]);
    srcbf[o] = tf32r(sv);
}

// ---------------- weight transpose+round+perm: W[K,N] -> Wt[n][k-perm] ------
__global__ void wtrans(const float* __restrict__ W, float* __restrict__ Wt, int K, int N)
{
    __shared__ float t[32][33];
    int n0 = blockIdx.x * 32, k0 = blockIdx.y * 32;
    int tx = threadIdx.x, ty = threadIdx.y;
    #pragma unroll
    for (int i = 0; i < 32; i += 8)
        t[ty + i][tx] = W[(size_t)(k0 + ty + i) * N + n0 + tx];
    __syncthreads();
    #pragma unroll
    for (int i = 0; i < 32; i += 8) {
        int n = ty + i;
        int ks = (tx & ~7) + sigf(tx & 7);
        Wt[(size_t)(n0 + n) * K + k0 + tx] = tf32r(t[ks][n]);
    }
}

// ---------------- fused add + LayerNorm (+ optional perm copy) --------------
__global__ void ln_kernel(const float* __restrict__ in1, int in1_sbd,
                          const float* __restrict__ in2,
                          const float* __restrict__ gamma, const float* __restrict__ beta,
                          float* __restrict__ out, int out_sbd,
                          float* __restrict__ xp)
{
    int m = blockIdx.x;
    int b = m / S_, s = m % S_;
    size_t sbd_off = ((size_t)(s * B_ + b)) * D_;
    size_t bf_off  = (size_t)m * D_;
    const float* p1 = in1 + (in1_sbd ? sbd_off : bf_off);
    const float* p2 = in2 + bf_off;
    float* po = out + (out_sbd ? sbd_off : bf_off);

    __shared__ float xs[D_];
    __shared__ float r1[256], r2[256];
    int tid = threadIdx.x;
    float s1 = 0.0f, s2 = 0.0f;
    for (int d = tid; d < D_; d += 256) {
        float v = p1[d] + p2[d];
        xs[d] = v; s1 += v; s2 += v * v;
    }
    r1[tid] = s1; r2[tid] = s2;
    __syncthreads();
    for (int st = 128; st > 0; st >>= 1) {
        if (tid < st) { r1[tid] += r1[tid + st]; r2[tid] += r2[tid + st]; }
        __syncthreads();
    }
    float mean = r1[0] * (1.0f / D_);
    float var  = r2[0] * (1.0f / D_) - mean * mean;
    float rstd = rsqrtf(var + 1e-5f);
    for (int d = tid; d < D_; d += 256) {
        float v = (xs[d] - mean) * rstd * gamma[d] + beta[d];
        po[d] = v;
        if (xp) {
            int ds = (d & ~7) + sigf(d & 7);
            float vp = (xs[ds] - mean) * rstd * gamma[ds] + beta[ds];
            xp[bf_off + d] = tf32r(vp);
        }
    }
}

// ---------------- launch ----------------
extern "C" void kernel_launch(void* const* d_in, const int* in_sizes, int n_in,
                              void* d_out, int out_size)
{
    static float *qkin = nullptr, *srcbf, *Qb, *Kb, *Vb, *ctx, *ao, *x, *h1, *f2,
                 *wr, *attn_fb;
    if (!qkin) {
        cudaGetSymbolAddress((void**)&qkin,  g_qkin);
        cudaGetSymbolAddress((void**)&srcbf, g_srcbf);
        cudaGetSymbolAddress((void**)&Qb,    g_Q);
        cudaGetSymbolAddress((void**)&Kb,    g_K);
        cudaGetSymbolAddress((void**)&Vb,    g_V);
        cudaGetSymbolAddress((void**)&ctx,   g_ctx);
        cudaGetSymbolAddress((void**)&ao,    g_ao);
        cudaGetSymbolAddress((void**)&x,     g_x);
        cudaGetSymbolAddress((void**)&h1,    g_h1);
        cudaGetSymbolAddress((void**)&f2,    g_f2);
        cudaGetSymbolAddress((void**)&wr,    g_wr);
        cudaGetSymbolAddress((void**)&attn_fb, g_attn_fb);
    }

    const float* src = (const float*)d_in[0];
    const float* pos = (const float*)d_in[1];
    const float* Wq  = (const float*)d_in[2];
    const float* bq  = (const float*)d_in[3];
    const float* Wk  = (const float*)d_in[4];
    const float* bk  = (const float*)d_in[5];
    const float* Wv  = (const float*)d_in[6];
    const float* bv  = (const float*)d_in[7];
    const float* Wo  = (const float*)d_in[8];
    const float* bo  = (const float*)d_in[9];
    const float* W1  = (const float*)d_in[10];
    const float* b1  = (const float*)d_in[11];
    const float* W2  = (const float*)d_in[12];
    const float* b2  = (const float*)d_in[13];
    const float* g1  = (const float*)d_in[14];
    const float* be1 = (const float*)d_in[15];
    const float* g2  = (const float*)d_in[16];
    const float* be2 = (const float*)d_in[17];

    float* out = (float*)d_out;
    long long need = (long long)S_ * B_ * D_ + (long long)B_ * H_ * S_ * S_;
    float* scores = attn_fb;
    float* probs  = ((long long)out_size >= need) ? out + (size_t)S_ * B_ * D_ : attn_fb;

    const int SMT = 2 * 10240 * 4;    // 81920 B
    const int SMA = 70144;
    cudaFuncSetAttribute(tgemm,      cudaFuncAttributeMaxDynamicSharedMemorySize, SMT);
    cudaFuncSetAttribute(av_softmax, cudaFuncAttributeMaxDynamicSharedMemorySize, SMA);

    float* wqr = wr;
    float* wkr = wr + 1048576;
    float* wvr = wr + 2097152;
    float* wor = wr + 3145728;
    float* w1r = wr + 4194304;
    float* w2r = wr + 8388608;

    // 1) prep
    dim3 wb(32, 8);
    wtrans<<<dim3(32, 32), wb>>>(Wq, wqr, 1024, 1024);
    wtrans<<<dim3(32, 32), wb>>>(Wk, wkr, 1024, 1024);
    wtrans<<<dim3(32, 32), wb>>>(Wv, wvr, 1024, 1024);
    wtrans<<<dim3(32, 32), wb>>>(Wo, wor, 1024, 1024);
    wtrans<<<dim3(128, 32), wb>>>(W1, w1r, 1024, 4096);
    wtrans<<<dim3(32, 128), wb>>>(W2, w2r, 4096, 1024);
    prep_kernel<<<32768, 256>>>(src, pos, qkin, srcbf);

    const long long SD = (long long)S_ * D_;
    const long long SS = (long long)S_ * S_;

    // 2-4) QKV projections (Q,K perm-out for scores; V natural)
    tgemm<<<dim3(8, 64, 1), 128, SMT>>>(qkin, wqr, bq, Qb,
        1024, D_, D_, D_, 1, 0, 0, 0, 0, 0, 0, 1.0f, 0, 1, 1);
    tgemm<<<dim3(8, 64, 1), 128, SMT>>>(qkin, wkr, bk, Kb,
        1024, D_, D_, D_, 1, 0, 0, 0, 0, 0, 0, 1.0f, 0, 1, 1);
    tgemm<<<dim3(8, 64, 1), 128, SMT>>>(srcbf, wvr, bv, Vb,
        1024, D_, D_, D_, 1, 0, 0, 0, 0, 0, 0, 1.0f, 0, 1, 0);

    // 5) scores = Q @ K^T / 8  (per (b,h): M=N=1024, K=64; both perm-d)
    tgemm<<<dim3(8, 8, B_ * H_), 128, SMT>>>(Qb, Kb, nullptr, scores,
        64, D_, D_, S_, H_,
        SD, 64, SD, 64, (long long)H_ * SS, SS, 0.125f, 0, 0, 0);

    // 6) fused softmax + probs + AV -> ctx (perm-d)
    av_softmax<<<dim3(8, B_ * H_), 256, SMA>>>(scores, Vb, probs, ctx);

    // 7) output projection
    tgemm<<<dim3(8, 64, 1), 128, SMT>>>(ctx, wor, bo, ao,
        1024, D_, D_, D_, 1, 0, 0, 0, 0, 0, 0, 1.0f, 0, 0, 0);

    // 8) LN1: x natural + xp perm (reuse Qb)
    float* xp = Qb;
    ln_kernel<<<M_TOK, 256>>>(src, 1, ao, g1, be1, x, 0, xp);

    // 9-10) FFN
    tgemm<<<dim3(32, 64, 1), 128, SMT>>>(xp, w1r, b1, h1,
        1024, D_, D_, F_, 1, 0, 0, 0, 0, 0, 0, 1.0f, 1, 1, 1);
    tgemm<<<dim3(8, 64, 1), 128, SMT>>>(h1, w2r, b2, f2,
        4096, F_, F_, D_, 1, 0, 0, 0, 0, 0, 0, 1.0f, 0, 0, 0);

    // 11) LN2 -> out
    ln_kernel<<<M_TOK, 256>>>(x, 0, f2, g2, be2, out, 1, nullptr);
}

// round 9
// speedup vs baseline: 1.2468x; 1.0047x over previous
#include <cuda_runtime.h>
#include <math.h>
#include <stdint.h>

#define S_ 1024
#define B_ 8
#define D_ 1024
#define H_ 16
#define F_ 4096
#define M_TOK (S_*B_)

// ---------------- scratch ----------------
__device__ float g_qkin[8388608];    // perm src+pos
__device__ float g_srcbf[8388608];   // perm src
__device__ float g_Q [8388608];      // Q perm (reused as xp later)
__device__ float g_K [8388608];      // K perm
__device__ float g_V [8388608];      // V natural
__device__ float g_ctx[8388608];     // ctx perm
__device__ float g_ao[8388608];
__device__ float g_x [8388608];      // LN1 natural
__device__ float g_h1[33554432];     // h1 perm
__device__ float g_f2[8388608];
__device__ float g_wr[12582912];     // W^T perm [n][k]
__device__ float g_psum[4194304];    // exp row-sum partials [bh][32][1024]
__device__ float g_attn_fb[134217728];

// position j holds original element sigf(j); invf = sigf^-1
__device__ __forceinline__ int sigf(int j) { return ((j & 1) << 2) + (j >> 1); }
__device__ __forceinline__ int invf(int p) { return ((p & 3) << 1) + (p >> 2); }

__device__ __forceinline__ float tf32r(float v) {
    unsigned r; asm("cvt.rna.tf32.f32 %0, %1;" : "=r"(r) : "f"(v));
    return __uint_as_float(r);
}
__device__ __forceinline__ void cp16(void* s, const void* g) {
    unsigned sa = (unsigned)__cvta_generic_to_shared(s);
    asm volatile("cp.async.ca.shared.global [%0], [%1], 16;" :: "r"(sa), "l"(g));
}
#define CP_COMMIT() asm volatile("cp.async.commit_group;")
#define CP_WAIT0()  asm volatile("cp.async.wait_group 0;")
#define CP_WAIT1()  asm volatile("cp.async.wait_group 1;")

__device__ __forceinline__ void mma_tf32(float* d, const unsigned* a, const unsigned* b) {
    asm volatile(
        "mma.sync.aligned.m16n8k8.row.col.f32.tf32.tf32.f32 "
        "{%0,%1,%2,%3}, {%4,%5,%6,%7}, {%8,%9}, {%0,%1,%2,%3};"
        : "+f"(d[0]), "+f"(d[1]), "+f"(d[2]), "+f"(d[3])
        : "r"(a[0]), "r"(a[1]), "r"(a[2]), "r"(a[3]), "r"(b[0]), "r"(b[1]));
}

// ================== tf32 GEMM: 128x128 CTA tile, 8 warps (64x32 each) ==================
// A[m][k], B[n][k] k-contiguous, both k sigma-permuted per 8-group.
// 2-stage cp.async, stride-40 smem rows (conflict-free per 16-lane phase).
// Optional psum: per-warp-chunk exp row sums (scores launch only).
__global__ void __launch_bounds__(256, 2) tgemm(
    const float* __restrict__ A, const float* __restrict__ Bm,
    const float* __restrict__ bias, float* __restrict__ C,
    float* __restrict__ psum,
    int K, int lda, int ldb, int ldc, int zdiv,
    long long sAh, long long sAl, long long sBh, long long sBl,
    long long sCh, long long sCl,
    float alpha, int relu, int rnd, int permout)
{
    extern __shared__ float smem[];      // 2 stages x (A 5120 + B 5120 floats)
    const int tid = threadIdx.x;
    const int wid = tid >> 5, lane = tid & 31;
    const int wm = wid & 1, wn = wid >> 1;        // 2 m-warps x 4 n-warps
    const int qr = lane >> 2, qc = lane & 3;
    const int m0 = blockIdx.y * 128;
    const int n0 = blockIdx.x * 128;
    const int z  = blockIdx.z;

    const float* Ag = A + (long long)(z / zdiv) * sAh + (long long)(z % zdiv) * sAl
                        + (size_t)m0 * lda;
    const float* Bg = Bm + (long long)(z / zdiv) * sBh + (long long)(z % zdiv) * sBl
                        + (size_t)n0 * ldb;
    float* Cg = C + (long long)(z / zdiv) * sCh + (long long)(z % zdiv) * sCl;

    auto ld_stage = [&](int s, int k0) {
        float* as = smem + s * 10240;
        float* bs = as + 5120;
        #pragma unroll
        for (int i = 0; i < 4; i++) {
            int idx = tid + i * 256;            // 1024 chunks: 128 rows x 8
            int r = idx >> 3, ch = idx & 7;
            cp16(&as[r * 40 + 4 * ch], Ag + (size_t)r * lda + k0 + 4 * ch);
        }
        #pragma unroll
        for (int i = 0; i < 4; i++) {
            int idx = tid + i * 256;
            int r = idx >> 3, ch = idx & 7;
            cp16(&bs[r * 40 + 4 * ch], Bg + (size_t)r * ldb + k0 + 4 * ch);
        }
    };

    float acc[4][4][4];
    #pragma unroll
    for (int mi = 0; mi < 4; mi++)
        #pragma unroll
        for (int ni = 0; ni < 4; ni++)
            #pragma unroll
            for (int j = 0; j < 4; j++) acc[mi][ni][j] = 0.0f;

    const int nk = K >> 5;
    ld_stage(0, 0);
    CP_COMMIT();

    for (int kt = 0; kt < nk; kt++) {
        if (kt + 1 < nk) {
            ld_stage((kt + 1) & 1, (kt + 1) << 5);
            CP_COMMIT();
            CP_WAIT1();
        } else {
            CP_WAIT0();
        }
        __syncthreads();
        const float* as = smem + (kt & 1) * 10240;
        const float* bs = as + 5120;

        #pragma unroll
        for (int kk = 0; kk < 4; kk++) {
            const int kx = (kk << 3) + (qc << 1);
            float2 fa[4][2];
            float2 fb[4];
            #pragma unroll
            for (int mi = 0; mi < 4; mi++) {
                int r = wm * 64 + mi * 16 + qr;
                fa[mi][0] = *(const float2*)&as[r * 40 + kx];
                fa[mi][1] = *(const float2*)&as[(r + 8) * 40 + kx];
            }
            #pragma unroll
            for (int ni = 0; ni < 4; ni++) {
                int n = wn * 32 + ni * 8 + qr;
                fb[ni] = *(const float2*)&bs[n * 40 + kx];
            }
            #pragma unroll
            for (int mi = 0; mi < 4; mi++) {
                unsigned a[4];
                a[0] = __float_as_uint(fa[mi][0].x);
                a[1] = __float_as_uint(fa[mi][1].x);
                a[2] = __float_as_uint(fa[mi][0].y);
                a[3] = __float_as_uint(fa[mi][1].y);
                #pragma unroll
                for (int ni = 0; ni < 4; ni++) {
                    unsigned b[2];
                    b[0] = __float_as_uint(fb[ni].x);
                    b[1] = __float_as_uint(fb[ni].y);
                    mma_tf32(acc[mi][ni], a, b);
                }
            }
        }
        __syncthreads();
    }

    // epilogue
    const int p0 = ((qc & 1) << 2) + (qc >> 1);   // invf(2qc)
    float es[4][2];
    #pragma unroll
    for (int mi = 0; mi < 4; mi++) { es[mi][0] = 0.0f; es[mi][1] = 0.0f; }

    #pragma unroll
    for (int mi = 0; mi < 4; mi++) {
        #pragma unroll
        for (int ni = 0; ni < 4; ni++) {
            int r0 = m0 + wm * 64 + mi * 16 + qr;
            int cg = n0 + wn * 32 + ni * 8;
            int c0 = cg + (qc << 1);
            float b0 = 0.0f, b1 = 0.0f;
            if (bias) { b0 = bias[c0]; b1 = bias[c0 + 1]; }
            #pragma unroll
            for (int h2 = 0; h2 < 2; h2++) {
                int row = r0 + h2 * 8;
                float v0 = fmaf(acc[mi][ni][h2 * 2 + 0], alpha, b0);
                float v1 = fmaf(acc[mi][ni][h2 * 2 + 1], alpha, b1);
                if (relu) { v0 = fmaxf(v0, 0.0f); v1 = fmaxf(v1, 0.0f); }
                if (rnd)  { v0 = tf32r(v0); v1 = tf32r(v1); }
                if (psum) es[mi][h2] += __expf(v0) + __expf(v1);
                if (permout) {
                    Cg[(size_t)row * ldc + cg + p0]     = v0;
                    Cg[(size_t)row * ldc + cg + p0 + 2] = v1;
                } else {
                    *(float2*)(Cg + (size_t)row * ldc + c0) = make_float2(v0, v1);
                }
            }
        }
    }

    if (psum) {
        int chunk = blockIdx.x * 4 + wn;
        #pragma unroll
        for (int mi = 0; mi < 4; mi++) {
            #pragma unroll
            for (int h2 = 0; h2 < 2; h2++) {
                float e = es[mi][h2];
                e += __shfl_xor_sync(0xffffffffu, e, 1);
                e += __shfl_xor_sync(0xffffffffu, e, 2);
                if (qc == 0) {
                    int row = m0 + wm * 64 + mi * 16 + qr + h2 * 8;
                    psum[((size_t)z * 32 + chunk) * 1024 + row] = e;
                }
            }
        }
    }
}

// ================== fused softmax + AV GEMM ==================
// Pass 1 now reads precomputed psum chunks (32 floats/row) instead of scores.
__global__ void __launch_bounds__(256, 2) av_softmax(
    const float* __restrict__ sc, const float* __restrict__ V,
    const float* __restrict__ psum,
    float* __restrict__ probs, float* __restrict__ ctx)
{
    extern __shared__ char sm[];
    float* as = (float*)sm;                       // [128][68] perm P slice
    float* vs = (float*)(sm + 34816);             // 2 x [64][68]
    float* rinv = (float*)(sm + 69632);           // [128]

    const int tid = threadIdx.x;
    const int w = tid >> 5, lane = tid & 31;
    const int wm = w & 3, wn = w >> 2;
    const int qr = lane >> 2, qc = lane & 3;
    const int bh = blockIdx.y, b = bh >> 4, h = bh & 15;
    const int m0 = blockIdx.x * 128;
    const float* scb = sc + ((size_t)bh << 20) + (size_t)m0 * 1024;
    float* prb = probs + ((size_t)bh << 20) + (size_t)m0 * 1024;

    {   // pass 1: row sums from psum partials
        int row = tid >> 1, half = tid & 1;
        const float* pp = psum + ((size_t)bh * 32) * 1024 + m0 + row;
        float s = 0.0f;
        #pragma unroll
        for (int c = 0; c < 16; c++) s += pp[(half * 16 + c) * 1024];
        s += __shfl_xor_sync(0xffffffffu, s, 1);
        if (half == 0) rinv[row] = 1.0f / s;
    }
    __syncthreads();

    auto ldV = [&](int kc) {
        float* dst = vs + (kc & 1) * (64 * 68);
        #pragma unroll
        for (int i = 0; i < 4; i++) {
            int idx = tid + i * 256;
            int r = idx >> 4, c4 = (idx & 15) << 2;
            cp16(&dst[r * 68 + c4],
                 &V[((size_t)(b * 1024 + kc * 64 + r)) * 1024 + h * 64 + c4]);
        }
    };

    float acc[2][4][4];
    #pragma unroll
    for (int mi = 0; mi < 2; mi++)
        #pragma unroll
        for (int ni = 0; ni < 4; ni++)
            #pragma unroll
            for (int j = 0; j < 4; j++) acc[mi][ni][j] = 0.0f;

    ldV(0);
    CP_COMMIT();

    for (int kc = 0; kc < 16; kc++) {
        #pragma unroll
        for (int i = 0; i < 8; i++) {
            int idx = tid + i * 256;
            int r = idx >> 4, c4 = (idx & 15) << 2;
            float inv = rinv[r];
            float4 x = *(const float4*)&scb[(size_t)r * 1024 + kc * 64 + c4];
            float4 p;
            p.x = __expf(x.x) * inv; p.y = __expf(x.y) * inv;
            p.z = __expf(x.z) * inv; p.w = __expf(x.w) * inv;
            *(float4*)&prb[(size_t)r * 1024 + kc * 64 + c4] = p;
            // sigma-permuted smem store
            int base = r * 68 + (c4 & ~7) + ((c4 & 7) ? 1 : 0);
            as[base + 0] = tf32r(p.x);
            as[base + 2] = tf32r(p.y);
            as[base + 4] = tf32r(p.z);
            as[base + 6] = tf32r(p.w);
        }
        if (kc + 1 < 16) { ldV(kc + 1); CP_COMMIT(); CP_WAIT1(); }
        else CP_WAIT0();
        __syncthreads();

        const float* vb = vs + (kc & 1) * (64 * 68);
        #pragma unroll
        for (int kk = 0; kk < 8; kk++) {
            unsigned a[2][4];
            int kx = kk * 8 + (qc << 1);
            #pragma unroll
            for (int mi = 0; mi < 2; mi++) {
                int r = wm * 32 + mi * 16 + qr;
                float2 f0 = *(const float2*)&as[r * 68 + kx];
                float2 f1 = *(const float2*)&as[(r + 8) * 68 + kx];
                a[mi][0] = __float_as_uint(f0.x);
                a[mi][1] = __float_as_uint(f1.x);
                a[mi][2] = __float_as_uint(f0.y);
                a[mi][3] = __float_as_uint(f1.y);
            }
            #pragma unroll
            for (int ni = 0; ni < 4; ni++) {
                int n = wn * 32 + ni * 8 + qr;
                unsigned bb[2];
                bb[0] = __float_as_uint(vb[(kk * 8 + qc) * 68 + n]);
                bb[1] = __float_as_uint(vb[(kk * 8 + qc + 4) * 68 + n]);
                #pragma unroll
                for (int mi = 0; mi < 2; mi++)
                    mma_tf32(acc[mi][ni], a[mi], bb);
            }
        }
        __syncthreads();
    }

    // epilogue -> ctx (perm within d 8-groups, tf32-rounded)
    const int p0 = ((qc & 1) << 2) + (qc >> 1);
    #pragma unroll
    for (int mi = 0; mi < 2; mi++) {
        #pragma unroll
        for (int ni = 0; ni < 4; ni++) {
            int r = m0 + wm * 32 + mi * 16 + qr;
            int cg = h * 64 + wn * 32 + ni * 8;
            size_t o0 = ((size_t)(b * 1024 + r)) * 1024 + cg;
            size_t o1 = ((size_t)(b * 1024 + r + 8)) * 1024 + cg;
            ctx[o0 + p0]     = tf32r(acc[mi][ni][0]);
            ctx[o0 + p0 + 2] = tf32r(acc[mi][ni][1]);
            ctx[o1 + p0]     = tf32r(acc[mi][ni][2]);
            ctx[o1 + p0 + 2] = tf32r(acc[mi][ni][3]);
        }
    }
}

// ---------------- prep: [S,B,D] -> batch-first perm (tf32-rounded) ----------
__global__ void prep_kernel(const float* __restrict__ src, const float* __restrict__ pos,
                            float* __restrict__ qkin, float* __restrict__ srcbf)
{
    size_t idx = (size_t)blockIdx.x * blockDim.x + threadIdx.x;
    if (idx >= (size_t)S_ * B_ * D_) return;
    int d = (int)(idx % D_);
    size_t sb = idx / D_;
    int b = (int)(sb % B_);
    int s = (int)(sb / B_);
    int dp = (d & ~7) + invf(d & 7);
    size_t o = ((size_t)(b * S_ + s)) * D_ + dp;
    float sv = src[idx];
    qkin[o]  = tf32r(sv + pos[idx]);
    srcbf[o] = tf32r(sv);
}

// ---------------- merged weight transpose+round+perm (all 6 weights) --------
__global__ void wprep(const float* __restrict__ Wq, const float* __restrict__ Wk,
                      const float* __restrict__ Wv, const float* __restrict__ Wo,
                      const float* __restrict__ W1, const float* __restrict__ W2,
                      float* __restrict__ wr)
{
    __shared__ float t[32][33];
    int bid = blockIdx.x;
    const float* W; float* Wt; int K, N, tt, nb;
    if (bid < 4096) {
        int w = bid >> 10; tt = bid & 1023; K = 1024; N = 1024; nb = 32;
        W = (w == 0) ? Wq : (w == 1) ? Wk : (w == 2) ? Wv : Wo;
        Wt = wr + (size_t)w * 1048576;
    } else if (bid < 8192) {
        tt = bid - 4096; K = 1024; N = 4096; nb = 128;
        W = W1; Wt = wr + 4194304;
    } else {
        tt = bid - 8192; K = 4096; N = 1024; nb = 32;
        W = W2; Wt = wr + 8388608;
    }
    int n0 = (tt % nb) * 32, k0 = (tt / nb) * 32;
    int tx = threadIdx.x, ty = threadIdx.y;
    #pragma unroll
    for (int i = 0; i < 32; i += 8)
        t[ty + i][tx] = W[(size_t)(k0 + ty + i) * N + n0 + tx];
    __syncthreads();
    #pragma unroll
    for (int i = 0; i < 32; i += 8) {
        int n = ty + i;
        int ks = (tx & ~7) + sigf(tx & 7);
        Wt[(size_t)(n0 + n) * K + k0 + tx] = tf32r(t[ks][n]);
    }
}

// ---------------- fused add + LayerNorm (+ optional perm copy) --------------
__global__ void ln_kernel(const float* __restrict__ in1, int in1_sbd,
                          const float* __restrict__ in2,
                          const float* __restrict__ gamma, const float* __restrict__ beta,
                          float* __restrict__ out, int out_sbd,
                          float* __restrict__ xp)
{
    int m = blockIdx.x;
    int b = m / S_, s = m % S_;
    size_t sbd_off = ((size_t)(s * B_ + b)) * D_;
    size_t bf_off  = (size_t)m * D_;
    const float* p1 = in1 + (in1_sbd ? sbd_off : bf_off);
    const float* p2 = in2 + bf_off;
    float* po = out + (out_sbd ? sbd_off : bf_off);

    __shared__ float xs[D_];
    __shared__ float r1[256], r2[256];
    int tid = threadIdx.x;
    float s1 = 0.0f, s2 = 0.0f;
    for (int d = tid; d < D_; d += 256) {
        float v = p1[d] + p2[d];
        xs[d] = v; s1 += v; s2 += v * v;
    }
    r1[tid] = s1; r2[tid] = s2;
    __syncthreads();
    for (int st = 128; st > 0; st >>= 1) {
        if (tid < st) { r1[tid] += r1[tid + st]; r2[tid] += r2[tid + st]; }
        __syncthreads();
    }
    float mean = r1[0] * (1.0f / D_);
    float var  = r2[0] * (1.0f / D_) - mean * mean;
    float rstd = rsqrtf(var + 1e-5f);
    for (int d = tid; d < D_; d += 256) {
        float v = (xs[d] - mean) * rstd * gamma[d] + beta[d];
        po[d] = v;
        if (xp) {
            int ds = (d & ~7) + sigf(d & 7);
            float vp = (xs[ds] - mean) * rstd * gamma[ds] + beta[ds];
            xp[bf_off + d] = tf32r(vp);
        }
    }
}

// ---------------- launch ----------------
extern "C" void kernel_launch(void* const* d_in, const int* in_sizes, int n_in,
                              void* d_out, int out_size)
{
    static float *qkin = nullptr, *srcbf, *Qb, *Kb, *Vb, *ctx, *ao, *x, *h1, *f2,
                 *wr, *psum, *attn_fb;
    if (!qkin) {
        cudaGetSymbolAddress((void**)&qkin,  g_qkin);
        cudaGetSymbolAddress((void**)&srcbf, g_srcbf);
        cudaGetSymbolAddress((void**)&Qb,    g_Q);
        cudaGetSymbolAddress((void**)&Kb,    g_K);
        cudaGetSymbolAddress((void**)&Vb,    g_V);
        cudaGetSymbolAddress((void**)&ctx,   g_ctx);
        cudaGetSymbolAddress((void**)&ao,    g_ao);
        cudaGetSymbolAddress((void**)&x,     g_x);
        cudaGetSymbolAddress((void**)&h1,    g_h1);
        cudaGetSymbolAddress((void**)&f2,    g_f2);
        cudaGetSymbolAddress((void**)&wr,    g_wr);
        cudaGetSymbolAddress((void**)&psum,  g_psum);
        cudaGetSymbolAddress((void**)&attn_fb, g_attn_fb);
    }

    const float* src = (const float*)d_in[0];
    const float* pos = (const float*)d_in[1];
    const float* Wq  = (const float*)d_in[2];
    const float* bq  = (const float*)d_in[3];
    const float* Wk  = (const float*)d_in[4];
    const float* bk  = (const float*)d_in[5];
    const float* Wv  = (const float*)d_in[6];
    const float* bv  = (const float*)d_in[7];
    const float* Wo  = (const float*)d_in[8];
    const float* bo  = (const float*)d_in[9];
    const float* W1  = (const float*)d_in[10];
    const float* b1  = (const float*)d_in[11];
    const float* W2  = (const float*)d_in[12];
    const float* b2  = (const float*)d_in[13];
    const float* g1  = (const float*)d_in[14];
    const float* be1 = (const float*)d_in[15];
    const float* g2  = (const float*)d_in[16];
    const float* be2 = (const float*)d_in[17];

    float* out = (float*)d_out;
    long long need = (long long)S_ * B_ * D_ + (long long)B_ * H_ * S_ * S_;
    float* scores = attn_fb;
    float* probs  = ((long long)out_size >= need) ? out + (size_t)S_ * B_ * D_ : attn_fb;

    const int SMT = 2 * 10240 * 4;    // 81920 B
    const int SMA = 70144;
    cudaFuncSetAttribute(tgemm,      cudaFuncAttributeMaxDynamicSharedMemorySize, SMT);
    cudaFuncSetAttribute(av_softmax, cudaFuncAttributeMaxDynamicSharedMemorySize, SMA);

    float* wqr = wr;
    float* wkr = wr + 1048576;
    float* wvr = wr + 2097152;
    float* wor = wr + 3145728;
    float* w1r = wr + 4194304;
    float* w2r = wr + 8388608;

    // 1) prep (merged weight transform + input prep)
    wprep<<<12288, dim3(32, 8)>>>(Wq, Wk, Wv, Wo, W1, W2, wr);
    prep_kernel<<<32768, 256>>>(src, pos, qkin, srcbf);

    const long long SD = (long long)S_ * D_;
    const long long SS = (long long)S_ * S_;

    // 2-4) QKV projections (Q,K perm-out for scores; V natural)
    tgemm<<<dim3(8, 64, 1), 256, SMT>>>(qkin, wqr, bq, Qb, nullptr,
        1024, D_, D_, D_, 1, 0, 0, 0, 0, 0, 0, 1.0f, 0, 1, 1);
    tgemm<<<dim3(8, 64, 1), 256, SMT>>>(qkin, wkr, bk, Kb, nullptr,
        1024, D_, D_, D_, 1, 0, 0, 0, 0, 0, 0, 1.0f, 0, 1, 1);
    tgemm<<<dim3(8, 64, 1), 256, SMT>>>(srcbf, wvr, bv, Vb, nullptr,
        1024, D_, D_, D_, 1, 0, 0, 0, 0, 0, 0, 1.0f, 0, 1, 0);

    // 5) scores = Q @ K^T / 8 + exp row-sum partials
    tgemm<<<dim3(8, 8, B_ * H_), 256, SMT>>>(Qb, Kb, nullptr, scores, psum,
        64, D_, D_, S_, H_,
        SD, 64, SD, 64, (long long)H_ * SS, SS, 0.125f, 0, 0, 0);

    // 6) fused softmax + probs + AV -> ctx (perm-d)
    av_softmax<<<dim3(8, B_ * H_), 256, SMA>>>(scores, Vb, psum, probs, ctx);

    // 7) output projection
    tgemm<<<dim3(8, 64, 1), 256, SMT>>>(ctx, wor, bo, ao, nullptr,
        1024, D_, D_, D_, 1, 0, 0, 0, 0, 0, 0, 1.0f, 0, 0, 0);

    // 8) LN1: x natural + xp perm (reuse Qb)
    float* xp = Qb;
    ln_kernel<<<M_TOK, 256>>>(src, 1, ao, g1, be1, x, 0, xp);

    // 9-10) FFN
    tgemm<<<dim3(32, 64, 1), 256, SMT>>>(xp, w1r, b1, h1, nullptr,
        1024, D_, D_, F_, 1, 0, 0, 0, 0, 0, 0, 1.0f, 1, 1, 1);
    tgemm<<<dim3(8, 64, 1), 256, SMT>>>(h1, w2r, b2, f2, nullptr,
        4096, F_, F_, D_, 1, 0, 0, 0, 0, 0, 0, 1.0f, 0, 0, 0);

    // 11) LN2 -> out
    ln_kernel<<<M_TOK, 256>>>(x, 0, f2, g2, be2, out, 1, nullptr);
}

// round 10
// speedup vs baseline: 2.0329x; 1.6305x over previous
#include <cuda_runtime.h>
#include <cuda_fp16.h>
#include <math.h>
#include <stdint.h>

#define S_ 1024
#define B_ 8
#define D_ 1024
#define H_ 16
#define F_ 4096
#define M_TOK (S_*B_)

// ---------------- scratch ----------------
__device__ __half g_qkin[8388608];   // perm16 src+pos fp16
__device__ __half g_srcbf[8388608];  // perm16 src fp16
__device__ __half g_Q [8388608];     // Q perm16 (reused as xp after attention)
__device__ __half g_K [8388608];     // K perm16
__device__ __half g_vt[8388608];     // V transposed per head [B,H,64,S] fp16 (t perm16)
__device__ __half g_ctx[8388608];    // ctx perm16 fp16
__device__ __half g_h1[33554432];    // h1 perm16 fp16
__device__ __half g_wr[12582912];    // W^T perm16 [n][k] fp16
__device__ float g_ao[8388608];
__device__ float g_x [8388608];
__device__ float g_f2[8388608];
__device__ float g_psum[4194304];    // exp row-sum partials [bh][32][1024]
__device__ float g_attn_fb[134217728];

// perm within 16-k groups: stored slot j holds orig k = sig16(j); inv16 = sig16^-1
// slots {4q,4q+1,4q+2,4q+3} = orig {2q,2q+1,2q+8,2q+9}
__device__ __forceinline__ int sig16(int j) {
    return ((j >> 2) << 1) + (j & 1) + ((j & 2) ? 8 : 0);
}
__device__ __forceinline__ int inv16(int p) {
    return 4 * ((p & 7) >> 1) + (p & 1) + ((p & 8) ? 2 : 0);
}

__device__ __forceinline__ void cp16(void* s, const void* g) {
    unsigned sa = (unsigned)__cvta_generic_to_shared(s);
    asm volatile("cp.async.ca.shared.global [%0], [%1], 16;" :: "r"(sa), "l"(g));
}
#define CP_COMMIT() asm volatile("cp.async.commit_group;")
#define CP_WAIT0()  asm volatile("cp.async.wait_group 0;")
#define CP_WAIT1()  asm volatile("cp.async.wait_group 1;")

__device__ __forceinline__ void mma_f16(float* d, const unsigned* a, const unsigned* b) {
    asm volatile(
        "mma.sync.aligned.m16n8k16.row.col.f32.f16.f16.f32 "
        "{%0,%1,%2,%3}, {%4,%5,%6,%7}, {%8,%9}, {%0,%1,%2,%3};"
        : "+f"(d[0]), "+f"(d[1]), "+f"(d[2]), "+f"(d[3])
        : "r"(a[0]), "r"(a[1]), "r"(a[2]), "r"(a[3]), "r"(b[0]), "r"(b[1]));
}
__device__ __forceinline__ unsigned packh(float a, float b) {
    __half2 t; t.x = __float2half(a); t.y = __float2half(b);
    return *(unsigned*)&t;
}

// ================== fp16 GEMM: 128x128 CTA tile, 8 warps (64x32 each) ==================
// A[m][k], B[n][k] fp16, k perm16'd. BK=64, 2-stage cp.async, stride-80 smem rows.
// mode: 0 = f32 out (+optional psum exp row sums), 1 = fp16 perm16 out, 2 = vt out.
__global__ void __launch_bounds__(256, 2) tgemm(
    const __half* __restrict__ A, const __half* __restrict__ Bm,
    const float* __restrict__ bias,
    float* __restrict__ Cf, __half* __restrict__ Ch, float* __restrict__ psum,
    int K, int lda, int ldb, int ldc, int zdiv,
    long long sAh, long long sAl, long long sBh, long long sBl,
    long long sCh, long long sCl,
    float alpha, int relu, int mode)
{
    extern __shared__ __half hsm[];      // 2 stages x (A 128x80 + B 128x80)
    const int tid = threadIdx.x;
    const int wid = tid >> 5, lane = tid & 31;
    const int wm = wid & 1, wn = wid >> 1;
    const int qr = lane >> 2, qc = lane & 3;
    const int m0 = blockIdx.y * 128;
    const int n0 = blockIdx.x * 128;
    const int z  = blockIdx.z;

    const __half* Ag = A + (long long)(z / zdiv) * sAh + (long long)(z % zdiv) * sAl
                         + (size_t)m0 * lda;
    const __half* Bg = Bm + (long long)(z / zdiv) * sBh + (long long)(z % zdiv) * sBl
                         + (size_t)n0 * ldb;
    float* Cg = Cf ? (Cf + (long long)(z / zdiv) * sCh + (long long)(z % zdiv) * sCl) : nullptr;

    auto ld_stage = [&](int s, int k0) {
        __half* as = hsm + s * 20480;
        __half* bs = as + 10240;
        #pragma unroll
        for (int i = 0; i < 4; i++) {           // A: 128 rows x 8 chunks of 8 halfs
            int idx = tid + i * 256;
            int r = idx >> 3, ch = idx & 7;
            cp16(&as[r * 80 + ch * 8], Ag + (size_t)r * lda + k0 + ch * 8);
        }
        #pragma unroll
        for (int i = 0; i < 4; i++) {
            int idx = tid + i * 256;
            int r = idx >> 3, ch = idx & 7;
            cp16(&bs[r * 80 + ch * 8], Bg + (size_t)r * ldb + k0 + ch * 8);
        }
    };

    float acc[4][4][4];
    #pragma unroll
    for (int mi = 0; mi < 4; mi++)
        #pragma unroll
        for (int ni = 0; ni < 4; ni++)
            #pragma unroll
            for (int j = 0; j < 4; j++) acc[mi][ni][j] = 0.0f;

    const int nk = K >> 6;
    ld_stage(0, 0);
    CP_COMMIT();

    for (int kt = 0; kt < nk; kt++) {
        if (kt + 1 < nk) {
            ld_stage((kt + 1) & 1, (kt + 1) << 6);
            CP_COMMIT();
            CP_WAIT1();
        } else {
            CP_WAIT0();
        }
        __syncthreads();
        const __half* as = hsm + (kt & 1) * 20480;
        const __half* bs = as + 10240;

        #pragma unroll
        for (int k16 = 0; k16 < 4; k16++) {
            const int kx = (k16 << 4) + (qc << 2);   // slots 4qc..4qc+3
            unsigned ua[4][4];
            unsigned ub[4][2];
            #pragma unroll
            for (int mi = 0; mi < 4; mi++) {
                int r = wm * 64 + mi * 16 + qr;
                uint2 u0 = *(const uint2*)&as[r * 80 + kx];
                uint2 u1 = *(const uint2*)&as[(r + 8) * 80 + kx];
                ua[mi][0] = u0.x; ua[mi][1] = u1.x;
                ua[mi][2] = u0.y; ua[mi][3] = u1.y;
            }
            #pragma unroll
            for (int ni = 0; ni < 4; ni++) {
                int n = wn * 32 + ni * 8 + qr;
                uint2 v = *(const uint2*)&bs[n * 80 + kx];
                ub[ni][0] = v.x; ub[ni][1] = v.y;
            }
            #pragma unroll
            for (int mi = 0; mi < 4; mi++)
                #pragma unroll
                for (int ni = 0; ni < 4; ni++)
                    mma_f16(acc[mi][ni], ua[mi], ub[ni]);
        }
        __syncthreads();
    }

    if (mode == 2) {
        // V-transpose epilogue: acc -> smem f32 -> Vt[b][h][d][t] fp16 (t perm16)
        float* fsm = (float*)hsm;                  // 128 x 132
        #pragma unroll
        for (int mi = 0; mi < 4; mi++)
            #pragma unroll
            for (int ni = 0; ni < 4; ni++) {
                int r = wm * 64 + mi * 16 + qr;
                int c = wn * 32 + ni * 8 + (qc << 1);
                #pragma unroll
                for (int h2 = 0; h2 < 2; h2++) {
                    fsm[(r + h2 * 8) * 132 + c]     = acc[mi][ni][h2 * 2 + 0] + bias[n0 + c];
                    fsm[(r + h2 * 8) * 132 + c + 1] = acc[mi][ni][h2 * 2 + 1] + bias[n0 + c + 1];
                }
            }
        __syncthreads();
        int b = m0 >> 10, t0 = m0 & 1023;
        for (int i = 0; i < 32; i++) {
            int idx = tid + i * 256;               // 8192 = 128 cols x 64 t-pairs
            int c = idx >> 6, tp = idx & 63;
            int t = tp * 2;
            int gc = n0 + c, h = gc >> 6, d = gc & 63;
            float v0 = fsm[t * 132 + c];
            float v1 = fsm[(t + 1) * 132 + c];
            int slot = (t & ~15) + inv16(t & 15);  // pairs map to adjacent slots
            *(unsigned*)&Ch[(((size_t)(b * H_ + h)) * 64 + d) * 1024 + t0 + slot] = packh(v0, v1);
        }
        return;
    }

    float es[4][2];
    #pragma unroll
    for (int mi = 0; mi < 4; mi++) { es[mi][0] = 0.0f; es[mi][1] = 0.0f; }

    if (mode == 1) {
        #pragma unroll
        for (int mi = 0; mi < 4; mi++)
            #pragma unroll
            for (int g = 0; g < 2; g++) {
                int cg16 = n0 + wn * 32 + g * 16;
                float bE0 = bias[cg16 + (qc << 1)],     bE1 = bias[cg16 + (qc << 1) + 1];
                float bO0 = bias[cg16 + 8 + (qc << 1)], bO1 = bias[cg16 + 8 + (qc << 1) + 1];
                #pragma unroll
                for (int h2 = 0; h2 < 2; h2++) {
                    int row = m0 + wm * 64 + mi * 16 + qr + h2 * 8;
                    float vE0 = acc[mi][2 * g + 0][h2 * 2 + 0] + bE0;
                    float vE1 = acc[mi][2 * g + 0][h2 * 2 + 1] + bE1;
                    float vO0 = acc[mi][2 * g + 1][h2 * 2 + 0] + bO0;
                    float vO1 = acc[mi][2 * g + 1][h2 * 2 + 1] + bO1;
                    if (relu) {
                        vE0 = fmaxf(vE0, 0.f); vE1 = fmaxf(vE1, 0.f);
                        vO0 = fmaxf(vO0, 0.f); vO1 = fmaxf(vO1, 0.f);
                    }
                    uint2 pk;
                    pk.x = packh(vE0, vE1);
                    pk.y = packh(vO0, vO1);
                    *(uint2*)&Ch[(size_t)row * ldc + cg16 + (qc << 2)] = pk;
                }
            }
    } else {
        #pragma unroll
        for (int mi = 0; mi < 4; mi++)
            #pragma unroll
            for (int ni = 0; ni < 4; ni++) {
                int c0 = n0 + wn * 32 + ni * 8 + (qc << 1);
                float b0 = 0.0f, b1 = 0.0f;
                if (bias) { b0 = bias[c0]; b1 = bias[c0 + 1]; }
                #pragma unroll
                for (int h2 = 0; h2 < 2; h2++) {
                    int row = m0 + wm * 64 + mi * 16 + qr + h2 * 8;
                    float v0 = fmaf(acc[mi][ni][h2 * 2 + 0], alpha, b0);
                    float v1 = fmaf(acc[mi][ni][h2 * 2 + 1], alpha, b1);
                    if (relu) { v0 = fmaxf(v0, 0.f); v1 = fmaxf(v1, 0.f); }
                    if (psum) es[mi][h2] += __expf(v0) + __expf(v1);
                    *(float2*)(Cg + (size_t)row * ldc + c0) = make_float2(v0, v1);
                }
            }
        if (psum) {
            int chunk = blockIdx.x * 4 + wn;
            #pragma unroll
            for (int mi = 0; mi < 4; mi++)
                #pragma unroll
                for (int h2 = 0; h2 < 2; h2++) {
                    float e = es[mi][h2];
                    e += __shfl_xor_sync(0xffffffffu, e, 1);
                    e += __shfl_xor_sync(0xffffffffu, e, 2);
                    if (qc == 0) {
                        int row = m0 + wm * 64 + mi * 16 + qr + h2 * 8;
                        psum[((size_t)z * 32 + chunk) * 1024 + row] = e;
                    }
                }
        }
    }
}

// ================== fused softmax + AV GEMM (fp16 MMA) ==================
// One CTA: 128 P-rows x DK=64 for one (b,h). P chunk fp16 perm16 in smem;
// V from Vt[b][h][d][t] (t perm16). ctx written fp16 perm16.
__global__ void __launch_bounds__(256, 2) av_softmax(
    const float* __restrict__ sc, const __half* __restrict__ Vt,
    const float* __restrict__ psum,
    float* __restrict__ probs, __half* __restrict__ ctx)
{
    extern __shared__ __half hsm[];
    __half* ph = hsm;                            // P chunk [128][80]
    __half* vs = hsm + 10240;                    // 2 x [64][80]
    float* rinv = (float*)(hsm + 10240 + 2 * 5120);   // [128]

    const int tid = threadIdx.x;
    const int w = tid >> 5, lane = tid & 31;
    const int wm = w & 3, wn = w >> 2;
    const int qr = lane >> 2, qc = lane & 3;
    const int bh = blockIdx.y;
    const int m0 = blockIdx.x * 128;
    const float* scb = sc + ((size_t)bh << 20) + (size_t)m0 * 1024;
    float* prb = probs + ((size_t)bh << 20) + (size_t)m0 * 1024;
    const __half* vtb = Vt + ((size_t)bh << 16);   // [64][1024]

    {   // pass 1: row sums from psum partials
        int row = tid >> 1, half = tid & 1;
        const float* pp = psum + ((size_t)bh * 32) * 1024 + m0 + row;
        float s = 0.0f;
        #pragma unroll
        for (int c = 0; c < 16; c++) s += pp[(half * 16 + c) * 1024];
        s += __shfl_xor_sync(0xffffffffu, s, 1);
        if (half == 0) rinv[row] = 1.0f / s;
    }
    __syncthreads();

    auto ldV = [&](int kc) {
        __half* dst = vs + (kc & 1) * 5120;
        #pragma unroll
        for (int i = 0; i < 2; i++) {            // 64 rows x 8 chunks
            int idx = tid + i * 256;
            int r = idx >> 3, ch = idx & 7;
            cp16(&dst[r * 80 + ch * 8], vtb + (size_t)r * 1024 + kc * 64 + ch * 8);
        }
    };

    float acc[2][4][4];
    #pragma unroll
    for (int mi = 0; mi < 2; mi++)
        #pragma unroll
        for (int ni = 0; ni < 4; ni++)
            #pragma unroll
            for (int j = 0; j < 4; j++) acc[mi][ni][j] = 0.0f;

    ldV(0);
    CP_COMMIT();

    for (int kc = 0; kc < 16; kc++) {
        // normalize chunk: probs write (f32, natural) + P fp16 perm16 in smem
        #pragma unroll
        for (int i = 0; i < 8; i++) {
            int idx = tid + i * 256;
            int r = idx >> 4, c4 = (idx & 15) << 2;
            float inv = rinv[r];
            float4 x = *(const float4*)&scb[(size_t)r * 1024 + kc * 64 + c4];
            float4 p;
            p.x = __expf(x.x) * inv; p.y = __expf(x.y) * inv;
            p.z = __expf(x.z) * inv; p.w = __expf(x.w) * inv;
            *(float4*)&prb[(size_t)r * 1024 + kc * 64 + c4] = p;
            int s0 = (c4 & ~15) + inv16(c4 & 15);
            *(unsigned*)&ph[r * 80 + s0]     = packh(p.x, p.y);
            *(unsigned*)&ph[r * 80 + s0 + 4] = packh(p.z, p.w);
        }
        if (kc + 1 < 16) { ldV(kc + 1); CP_COMMIT(); CP_WAIT1(); }
        else CP_WAIT0();
        __syncthreads();

        const __half* vb = vs + (kc & 1) * 5120;
        #pragma unroll
        for (int k16 = 0; k16 < 4; k16++) {
            const int kx = (k16 << 4) + (qc << 2);
            unsigned ua[2][4], ub[4][2];
            #pragma unroll
            for (int mi = 0; mi < 2; mi++) {
                int r = wm * 32 + mi * 16 + qr;
                uint2 u0 = *(const uint2*)&ph[r * 80 + kx];
                uint2 u1 = *(const uint2*)&ph[(r + 8) * 80 + kx];
                ua[mi][0] = u0.x; ua[mi][1] = u1.x;
                ua[mi][2] = u0.y; ua[mi][3] = u1.y;
            }
            #pragma unroll
            for (int ni = 0; ni < 4; ni++) {
                int n = wn * 32 + ni * 8 + qr;
                uint2 v = *(const uint2*)&vb[n * 80 + kx];
                ub[ni][0] = v.x; ub[ni][1] = v.y;
            }
            #pragma unroll
            for (int mi = 0; mi < 2; mi++)
                #pragma unroll
                for (int ni = 0; ni < 4; ni++)
                    mma_f16(acc[mi][ni], ua[mi], ub[ni]);
        }
        __syncthreads();
    }

    // epilogue -> ctx fp16 perm16
    const int b = bh >> 4, h = bh & 15;
    #pragma unroll
    for (int mi = 0; mi < 2; mi++)
        #pragma unroll
        for (int g = 0; g < 2; g++) {
            int cg16 = h * 64 + wn * 32 + g * 16;
            #pragma unroll
            for (int h2 = 0; h2 < 2; h2++) {
                int r = m0 + wm * 32 + mi * 16 + qr + h2 * 8;
                uint2 pk;
                pk.x = packh(acc[mi][2 * g + 0][h2 * 2 + 0], acc[mi][2 * g + 0][h2 * 2 + 1]);
                pk.y = packh(acc[mi][2 * g + 1][h2 * 2 + 0], acc[mi][2 * g + 1][h2 * 2 + 1]);
                *(uint2*)&ctx[((size_t)(b * 1024 + r)) * 1024 + cg16 + (qc << 2)] = pk;
            }
        }
}

// ---------------- prep: [S,B,D] -> batch-first fp16 perm16 ----------------
__global__ void prep_kernel(const float* __restrict__ src, const float* __restrict__ pos,
                            __half* __restrict__ qkin, __half* __restrict__ srcbf)
{
    size_t idx = (size_t)blockIdx.x * blockDim.x + threadIdx.x;
    if (idx >= (size_t)S_ * B_ * D_) return;
    int d = (int)(idx % D_);
    size_t sb = idx / D_;
    int b = (int)(sb % B_);
    int s = (int)(sb / B_);
    int dp = (d & ~15) + inv16(d & 15);
    size_t o = ((size_t)(b * S_ + s)) * D_ + dp;
    float sv = src[idx];
    qkin[o]  = __float2half(sv + pos[idx]);
    srcbf[o] = __float2half(sv);
}

// ---------------- merged weight transpose+perm16 (all 6 weights, fp16) ------
__global__ void wprep(const float* __restrict__ Wq, const float* __restrict__ Wk,
                      const float* __restrict__ Wv, const float* __restrict__ Wo,
                      const float* __restrict__ W1, const float* __restrict__ W2,
                      __half* __restrict__ wr)
{
    __shared__ float t[32][33];
    int bid = blockIdx.x;
    const float* W; __half* Wt; int K, N, tt, nb;
    if (bid < 4096) {
        int w = bid >> 10; tt = bid & 1023; K = 1024; N = 1024; nb = 32;
        W = (w == 0) ? Wq : (w == 1) ? Wk : (w == 2) ? Wv : Wo;
        Wt = wr + (size_t)w * 1048576;
    } else if (bid < 8192) {
        tt = bid - 4096; K = 1024; N = 4096; nb = 128;
        W = W1; Wt = wr + 4194304;
    } else {
        tt = bid - 8192; K = 4096; N = 1024; nb = 32;
        W = W2; Wt = wr + 8388608;
    }
    int n0 = (tt % nb) * 32, k0 = (tt / nb) * 32;
    int tx = threadIdx.x, ty = threadIdx.y;
    #pragma unroll
    for (int i = 0; i < 32; i += 8)
        t[ty + i][tx] = W[(size_t)(k0 + ty + i) * N + n0 + tx];
    __syncthreads();
    #pragma unroll
    for (int i = 0; i < 32; i += 8) {
        int n = ty + i;
        int ks = (tx & ~15) + sig16(tx & 15);
        Wt[(size_t)(n0 + n) * K + k0 + tx] = __float2half(t[ks][n]);
    }
}

// ---------------- fused add + LayerNorm (+ optional fp16 perm16 copy) -------
__global__ void ln_kernel(const float* __restrict__ in1, int in1_sbd,
                          const float* __restrict__ in2,
                          const float* __restrict__ gamma, const float* __restrict__ beta,
                          float* __restrict__ out, int out_sbd,
                          __half* __restrict__ xp)
{
    int m = blockIdx.x;
    int b = m / S_, s = m % S_;
    size_t sbd_off = ((size_t)(s * B_ + b)) * D_;
    size_t bf_off  = (size_t)m * D_;
    const float* p1 = in1 + (in1_sbd ? sbd_off : bf_off);
    const float* p2 = in2 + bf_off;
    float* po = out + (out_sbd ? sbd_off : bf_off);

    __shared__ float xs[D_];
    __shared__ float r1[256], r2[256];
    int tid = threadIdx.x;
    float s1 = 0.0f, s2 = 0.0f;
    for (int d = tid; d < D_; d += 256) {
        float v = p1[d] + p2[d];
        xs[d] = v; s1 += v; s2 += v * v;
    }
    r1[tid] = s1; r2[tid] = s2;
    __syncthreads();
    for (int st = 128; st > 0; st >>= 1) {
        if (tid < st) { r1[tid] += r1[tid + st]; r2[tid] += r2[tid + st]; }
        __syncthreads();
    }
    float mean = r1[0] * (1.0f / D_);
    float var  = r2[0] * (1.0f / D_) - mean * mean;
    float rstd = rsqrtf(var + 1e-5f);
    for (int d = tid; d < D_; d += 256) {
        float v = (xs[d] - mean) * rstd * gamma[d] + beta[d];
        po[d] = v;
        if (xp) {
            int ds = (d & ~15) + sig16(d & 15);
            float vp = (xs[ds] - mean) * rstd * gamma[ds] + beta[ds];
            xp[bf_off + d] = __float2half(vp);
        }
    }
}

// ---------------- launch ----------------
extern "C" void kernel_launch(void* const* d_in, const int* in_sizes, int n_in,
                              void* d_out, int out_size)
{
    static __half *qkin = nullptr, *srcbf, *Qh, *Kh, *vt, *ctxh, *h1, *wr;
    static float *ao, *x, *f2, *psum, *attn_fb;
    if (!qkin) {
        cudaGetSymbolAddress((void**)&qkin,  g_qkin);
        cudaGetSymbolAddress((void**)&srcbf, g_srcbf);
        cudaGetSymbolAddress((void**)&Qh,    g_Q);
        cudaGetSymbolAddress((void**)&Kh,    g_K);
        cudaGetSymbolAddress((void**)&vt,    g_vt);
        cudaGetSymbolAddress((void**)&ctxh,  g_ctx);
        cudaGetSymbolAddress((void**)&h1,    g_h1);
        cudaGetSymbolAddress((void**)&wr,    g_wr);
        cudaGetSymbolAddress((void**)&ao,    g_ao);
        cudaGetSymbolAddress((void**)&x,     g_x);
        cudaGetSymbolAddress((void**)&f2,    g_f2);
        cudaGetSymbolAddress((void**)&psum,  g_psum);
        cudaGetSymbolAddress((void**)&attn_fb, g_attn_fb);
    }

    const float* src = (const float*)d_in[0];
    const float* pos = (const float*)d_in[1];
    const float* Wq  = (const float*)d_in[2];
    const float* bq  = (const float*)d_in[3];
    const float* Wk  = (const float*)d_in[4];
    const float* bk  = (const float*)d_in[5];
    const float* Wv  = (const float*)d_in[6];
    const float* bv  = (const float*)d_in[7];
    const float* Wo  = (const float*)d_in[8];
    const float* bo  = (const float*)d_in[9];
    const float* W1  = (const float*)d_in[10];
    const float* b1  = (const float*)d_in[11];
    const float* W2  = (const float*)d_in[12];
    const float* b2  = (const float*)d_in[13];
    const float* g1  = (const float*)d_in[14];
    const float* be1 = (const float*)d_in[15];
    const float* g2  = (const float*)d_in[16];
    const float* be2 = (const float*)d_in[17];

    float* out = (float*)d_out;
    long long need = (long long)S_ * B_ * D_ + (long long)B_ * H_ * S_ * S_;
    float* scores = attn_fb;
    float* probs  = ((long long)out_size >= need) ? out + (size_t)S_ * B_ * D_ : attn_fb;

    const int SMT = 2 * 20480 * 2;                 // 81920 B
    const int SMA = 10240 * 2 + 2 * 5120 * 2 + 512; // P + 2xV + rinv = 41472 B
    cudaFuncSetAttribute(tgemm,      cudaFuncAttributeMaxDynamicSharedMemorySize, SMT);
    cudaFuncSetAttribute(av_softmax, cudaFuncAttributeMaxDynamicSharedMemorySize, SMA);

    __half* wqr = wr;
    __half* wkr = wr + 1048576;
    __half* wvr = wr + 2097152;
    __half* wor = wr + 3145728;
    __half* w1r = wr + 4194304;
    __half* w2r = wr + 8388608;

    // 1) prep
    wprep<<<12288, dim3(32, 8)>>>(Wq, Wk, Wv, Wo, W1, W2, wr);
    prep_kernel<<<32768, 256>>>(src, pos, qkin, srcbf);

    const long long SD = (long long)S_ * D_;
    const long long SS = (long long)S_ * S_;

    // 2-4) QKV projections: Q,K fp16 perm16; V -> transposed fp16 Vt
    tgemm<<<dim3(8, 64, 1), 256, SMT>>>(qkin, wqr, bq, nullptr, Qh, nullptr,
        1024, D_, D_, D_, 1, 0, 0, 0, 0, 0, 0, 1.0f, 0, 1);
    tgemm<<<dim3(8, 64, 1), 256, SMT>>>(qkin, wkr, bk, nullptr, Kh, nullptr,
        1024, D_, D_, D_, 1, 0, 0, 0, 0, 0, 0, 1.0f, 0, 1);
    tgemm<<<dim3(8, 64, 1), 256, SMT>>>(srcbf, wvr, bv, nullptr, vt, nullptr,
        1024, D_, D_, D_, 1, 0, 0, 0, 0, 0, 0, 1.0f, 0, 2);

    // 5) scores = Q @ K^T / 8 (f32 out) + exp row-sum partials
    tgemm<<<dim3(8, 8, B_ * H_), 256, SMT>>>(Qh, Kh, nullptr, scores, nullptr, psum,
        64, D_, D_, S_, H_,
        SD, 64, SD, 64, (long long)H_ * SS, SS, 0.125f, 0, 0);

    // 6) fused softmax + probs + AV -> ctx fp16 perm16
    av_softmax<<<dim3(8, B_ * H_), 256, SMA>>>(scores, vt, psum, probs, ctxh);

    // 7) output projection (f32 out)
    tgemm<<<dim3(8, 64, 1), 256, SMT>>>(ctxh, wor, bo, ao, nullptr, nullptr,
        1024, D_, D_, D_, 1, 0, 0, 0, 0, 0, 0, 1.0f, 0, 0);

    // 8) LN1: x f32 + xp fp16 perm16 (reuse Qh)
    __half* xp = Qh;
    ln_kernel<<<M_TOK, 256>>>(src, 1, ao, g1, be1, x, 0, xp);

    // 9-10) FFN
    tgemm<<<dim3(32, 64, 1), 256, SMT>>>(xp, w1r, b1, nullptr, h1, nullptr,
        1024, D_, D_, F_, 1, 0, 0, 0, 0, 0, 0, 1.0f, 1, 1);
    tgemm<<<dim3(8, 64, 1), 256, SMT>>>(h1, w2r, b2, f2, nullptr, nullptr,
        4096, F_, F_, D_, 1, 0, 0, 0, 0, 0, 0, 1.0f, 0, 0);

    // 11) LN2 -> out
    ln_kernel<<<M_TOK, 256>>>(x, 0, f2, g2, be2, out, 1, nullptr);
}

// round 12
// speedup vs baseline: 2.2343x; 1.0991x over previous
#include <cuda_runtime.h>
#include <cuda_fp16.h>
#include <math.h>
#include <stdint.h>

#define S_ 1024
#define B_ 8
#define D_ 1024
#define H_ 16
#define F_ 4096
#define M_TOK (S_*B_)

// ---------------- scratch ----------------
__device__ __half g_qkin[8388608];   // perm16 src+pos fp16
__device__ __half g_srcbf[8388608];  // perm16 src fp16
__device__ __half g_Q [8388608];     // Q perm16 (reused as xp after attention)
__device__ __half g_K [8388608];     // K perm16
__device__ __half g_vt[8388608];     // V transposed per head [B,H,64,S] fp16 (t perm16)
__device__ __half g_ctx[8388608];    // ctx perm16 fp16
__device__ __half g_h1[33554432];    // h1 perm16 fp16
__device__ __half g_wr[12582912];    // W^T perm16 [n][k] fp16
__device__ float g_ao[8388608];
__device__ float g_x [8388608];
__device__ float g_f2[8388608];
__device__ float g_psum[4194304];    // exp row-sum partials [bh][32][1024]
__device__ float g_attn_fb[134217728];

// perm within 16-k groups: stored slot j holds orig k = sig16(j); inv16 = sig16^-1
// slots {4q,4q+1,4q+2,4q+3} = orig {2q,2q+1,2q+8,2q+9}
__device__ __forceinline__ int sig16(int j) {
    return ((j >> 2) << 1) + (j & 1) + ((j & 2) ? 8 : 0);
}
__device__ __forceinline__ int inv16(int p) {
    return 4 * ((p & 7) >> 1) + (p & 1) + ((p & 8) ? 2 : 0);
}

__device__ __forceinline__ void cp16(void* s, const void* g) {
    unsigned sa = (unsigned)__cvta_generic_to_shared(s);
    asm volatile("cp.async.ca.shared.global [%0], [%1], 16;" :: "r"(sa), "l"(g));
}
#define CP_COMMIT() asm volatile("cp.async.commit_group;")
#define CP_WAIT0()  asm volatile("cp.async.wait_group 0;")
#define CP_WAIT1()  asm volatile("cp.async.wait_group 1;")

__device__ __forceinline__ void mma_f16(float* d, const unsigned* a, const unsigned* b) {
    asm volatile(
        "mma.sync.aligned.m16n8k16.row.col.f32.f16.f16.f32 "
        "{%0,%1,%2,%3}, {%4,%5,%6,%7}, {%8,%9}, {%0,%1,%2,%3};"
        : "+f"(d[0]), "+f"(d[1]), "+f"(d[2]), "+f"(d[3])
        : "r"(a[0]), "r"(a[1]), "r"(a[2]), "r"(a[3]), "r"(b[0]), "r"(b[1]));
}
__device__ __forceinline__ unsigned packh(float a, float b) {
    __half2 t; t.x = __float2half(a); t.y = __float2half(b);
    return *(unsigned*)&t;
}

// ================== fp16 GEMM: 128x128 CTA tile, 8 warps (64x32 each) ==================
// A[m][k], B[n][k] fp16, k perm16'd. BK=64, 2-stage cp.async, stride-80 smem rows.
// mode: 0 = f32 out (Cf may be null -> psum only), 1 = fp16 perm16 out, 2 = vt out.
__global__ void __launch_bounds__(256, 2) tgemm(
    const __half* __restrict__ A, const __half* __restrict__ Bm,
    const float* __restrict__ bias,
    float* __restrict__ Cf, __half* __restrict__ Ch, float* __restrict__ psum,
    int K, int lda, int ldb, int ldc, int zdiv,
    long long sAh, long long sAl, long long sBh, long long sBl,
    long long sCh, long long sCl,
    float alpha, int relu, int mode)
{
    extern __shared__ __half hsm[];      // 2 stages x (A 128x80 + B 128x80)
    const int tid = threadIdx.x;
    const int wid = tid >> 5, lane = tid & 31;
    const int wm = wid & 1, wn = wid >> 1;
    const int qr = lane >> 2, qc = lane & 3;
    const int m0 = blockIdx.y * 128;
    const int n0 = blockIdx.x * 128;
    const int z  = blockIdx.z;

    const __half* Ag = A + (long long)(z / zdiv) * sAh + (long long)(z % zdiv) * sAl
                         + (size_t)m0 * lda;
    const __half* Bg = Bm + (long long)(z / zdiv) * sBh + (long long)(z % zdiv) * sBl
                         + (size_t)n0 * ldb;
    float* Cg = Cf ? (Cf + (long long)(z / zdiv) * sCh + (long long)(z % zdiv) * sCl) : nullptr;

    auto ld_stage = [&](int s, int k0) {
        __half* as = hsm + s * 20480;
        __half* bs = as + 10240;
        #pragma unroll
        for (int i = 0; i < 4; i++) {
            int idx = tid + i * 256;
            int r = idx >> 3, ch = idx & 7;
            cp16(&as[r * 80 + ch * 8], Ag + (size_t)r * lda + k0 + ch * 8);
        }
        #pragma unroll
        for (int i = 0; i < 4; i++) {
            int idx = tid + i * 256;
            int r = idx >> 3, ch = idx & 7;
            cp16(&bs[r * 80 + ch * 8], Bg + (size_t)r * ldb + k0 + ch * 8);
        }
    };

    float acc[4][4][4];
    #pragma unroll
    for (int mi = 0; mi < 4; mi++)
        #pragma unroll
        for (int ni = 0; ni < 4; ni++)
            #pragma unroll
            for (int j = 0; j < 4; j++) acc[mi][ni][j] = 0.0f;

    const int nk = K >> 6;
    ld_stage(0, 0);
    CP_COMMIT();

    for (int kt = 0; kt < nk; kt++) {
        if (kt + 1 < nk) {
            ld_stage((kt + 1) & 1, (kt + 1) << 6);
            CP_COMMIT();
            CP_WAIT1();
        } else {
            CP_WAIT0();
        }
        __syncthreads();
        const __half* as = hsm + (kt & 1) * 20480;
        const __half* bs = as + 10240;

        #pragma unroll
        for (int k16 = 0; k16 < 4; k16++) {
            const int kx = (k16 << 4) + (qc << 2);
            unsigned ua[4][4];
            unsigned ub[4][2];
            #pragma unroll
            for (int mi = 0; mi < 4; mi++) {
                int r = wm * 64 + mi * 16 + qr;
                uint2 u0 = *(const uint2*)&as[r * 80 + kx];
                uint2 u1 = *(const uint2*)&as[(r + 8) * 80 + kx];
                ua[mi][0] = u0.x; ua[mi][1] = u1.x;
                ua[mi][2] = u0.y; ua[mi][3] = u1.y;
            }
            #pragma unroll
            for (int ni = 0; ni < 4; ni++) {
                int n = wn * 32 + ni * 8 + qr;
                uint2 v = *(const uint2*)&bs[n * 80 + kx];
                ub[ni][0] = v.x; ub[ni][1] = v.y;
            }
            #pragma unroll
            for (int mi = 0; mi < 4; mi++)
                #pragma unroll
                for (int ni = 0; ni < 4; ni++)
                    mma_f16(acc[mi][ni], ua[mi], ub[ni]);
        }
        __syncthreads();
    }

    if (mode == 2) {
        // V-transpose epilogue: acc -> smem f32 -> Vt[b][h][d][t] fp16 (t perm16)
        float* fsm = (float*)hsm;                  // 128 x 132
        #pragma unroll
        for (int mi = 0; mi < 4; mi++)
            #pragma unroll
            for (int ni = 0; ni < 4; ni++) {
                int r = wm * 64 + mi * 16 + qr;
                int c = wn * 32 + ni * 8 + (qc << 1);
                #pragma unroll
                for (int h2 = 0; h2 < 2; h2++) {
                    fsm[(r + h2 * 8) * 132 + c]     = acc[mi][ni][h2 * 2 + 0] + bias[n0 + c];
                    fsm[(r + h2 * 8) * 132 + c + 1] = acc[mi][ni][h2 * 2 + 1] + bias[n0 + c + 1];
                }
            }
        __syncthreads();
        int b = m0 >> 10, t0 = m0 & 1023;
        for (int i = 0; i < 32; i++) {
            int idx = tid + i * 256;
            int c = idx >> 6, tp = idx & 63;
            int t = tp * 2;
            int gc = n0 + c, h = gc >> 6, d = gc & 63;
            float v0 = fsm[t * 132 + c];
            float v1 = fsm[(t + 1) * 132 + c];
            int slot = (t & ~15) + inv16(t & 15);
            *(unsigned*)&Ch[(((size_t)(b * H_ + h)) * 64 + d) * 1024 + t0 + slot] = packh(v0, v1);
        }
        return;
    }

    float es[4][2];
    #pragma unroll
    for (int mi = 0; mi < 4; mi++) { es[mi][0] = 0.0f; es[mi][1] = 0.0f; }

    if (mode == 1) {
        #pragma unroll
        for (int mi = 0; mi < 4; mi++)
            #pragma unroll
            for (int g = 0; g < 2; g++) {
                int cg16 = n0 + wn * 32 + g * 16;
                float bE0 = bias[cg16 + (qc << 1)],     bE1 = bias[cg16 + (qc << 1) + 1];
                float bO0 = bias[cg16 + 8 + (qc << 1)], bO1 = bias[cg16 + 8 + (qc << 1) + 1];
                #pragma unroll
                for (int h2 = 0; h2 < 2; h2++) {
                    int row = m0 + wm * 64 + mi * 16 + qr + h2 * 8;
                    float vE0 = acc[mi][2 * g + 0][h2 * 2 + 0] + bE0;
                    float vE1 = acc[mi][2 * g + 0][h2 * 2 + 1] + bE1;
                    float vO0 = acc[mi][2 * g + 1][h2 * 2 + 0] + bO0;
                    float vO1 = acc[mi][2 * g + 1][h2 * 2 + 1] + bO1;
                    if (relu) {
                        vE0 = fmaxf(vE0, 0.f); vE1 = fmaxf(vE1, 0.f);
                        vO0 = fmaxf(vO0, 0.f); vO1 = fmaxf(vO1, 0.f);
                    }
                    uint2 pk;
                    pk.x = packh(vE0, vE1);
                    pk.y = packh(vO0, vO1);
                    *(uint2*)&Ch[(size_t)row * ldc + cg16 + (qc << 2)] = pk;
                }
            }
    } else {
        #pragma unroll
        for (int mi = 0; mi < 4; mi++)
            #pragma unroll
            for (int ni = 0; ni < 4; ni++) {
                int c0 = n0 + wn * 32 + ni * 8 + (qc << 1);
                float b0 = 0.0f, b1 = 0.0f;
                if (bias) { b0 = bias[c0]; b1 = bias[c0 + 1]; }
                #pragma unroll
                for (int h2 = 0; h2 < 2; h2++) {
                    int row = m0 + wm * 64 + mi * 16 + qr + h2 * 8;
                    float v0 = fmaf(acc[mi][ni][h2 * 2 + 0], alpha, b0);
                    float v1 = fmaf(acc[mi][ni][h2 * 2 + 1], alpha, b1);
                    if (relu) { v0 = fmaxf(v0, 0.f); v1 = fmaxf(v1, 0.f); }
                    if (psum) es[mi][h2] += __expf(v0) + __expf(v1);
                    if (Cg)
                        *(float2*)(Cg + (size_t)row * ldc + c0) = make_float2(v0, v1);
                }
            }
        if (psum) {
            int chunk = blockIdx.x * 4 + wn;
            #pragma unroll
            for (int mi = 0; mi < 4; mi++)
                #pragma unroll
                for (int h2 = 0; h2 < 2; h2++) {
                    float e = es[mi][h2];
                    e += __shfl_xor_sync(0xffffffffu, e, 1);
                    e += __shfl_xor_sync(0xffffffffu, e, 2);
                    if (qc == 0) {
                        int row = m0 + wm * 64 + mi * 16 + qr + h2 * 8;
                        psum[((size_t)z * 32 + chunk) * 1024 + row] = e;
                    }
                }
        }
    }
}

// ================== fully fused attention: recompute S + softmax + probs + AV ==========
// One CTA: 128 q-rows of one (b,h). Q tile resident in smem; K/V chunks streamed
// (double-buffered). S recomputed (bit-identical to psum pass), p = exp(s)*rinv,
// probs written once (f32), P round-trips smem as fp16 perm16, AV accumulates.
__global__ void __launch_bounds__(256, 2) attn_fused(
    const __half* __restrict__ Qh, const __half* __restrict__ Kh,
    const __half* __restrict__ Vt, const float* __restrict__ psum,
    float* __restrict__ probs, __half* __restrict__ ctx)
{
    extern __shared__ __half hsm[];
    __half* qs = hsm;                             // [128][80]
    __half* kb = hsm + 10240;                     // 2 x [64][80]
    __half* vb = hsm + 20480;                     // 2 x [64][80]
    __half* ph = hsm + 30720;                     // [128][80]
    float* rinv = (float*)(hsm + 40960);          // [128]

    const int tid = threadIdx.x;
    const int w = tid >> 5, lane = tid & 31;
    const int wm = w & 3, wn = w >> 2;            // 4 m x 2 n (32x32 tiles)
    const int qr = lane >> 2, qc = lane & 3;
    const int bh = blockIdx.y, b = bh >> 4, h = bh & 15;
    const int m0 = blockIdx.x * 128;
    float* prb = probs + ((size_t)bh << 20) + (size_t)m0 * 1024;
    const __half* qg = Qh + ((size_t)(b * 1024 + m0)) * 1024 + h * 64;
    const __half* kg = Kh + ((size_t)(b * 1024)) * 1024 + h * 64;
    const __half* vtb = Vt + ((size_t)bh << 16);  // [64][1024]

    {   // row sums from psum partials
        int row = tid >> 1, half = tid & 1;
        const float* pp = psum + ((size_t)bh * 32) * 1024 + m0 + row;
        float s = 0.0f;
        #pragma unroll
        for (int c = 0; c < 16; c++) s += pp[(half * 16 + c) * 1024];
        s += __shfl_xor_sync(0xffffffffu, s, 1);
        if (half == 0) rinv[row] = 1.0f / s;
    }

    // load Q tile [128][64]
    #pragma unroll
    for (int i = 0; i < 4; i++) {
        int idx = tid + i * 256;
        int r = idx >> 3, ch = idx & 7;
        cp16(&qs[r * 80 + ch * 8], qg + (size_t)r * 1024 + ch * 8);
    }

    auto ldKV = [&](int kc) {
        __half* kd = kb + (kc & 1) * 5120;
        __half* vd = vb + (kc & 1) * 5120;
        #pragma unroll
        for (int i = 0; i < 2; i++) {
            int idx = tid + i * 256;
            int r = idx >> 3, ch = idx & 7;
            cp16(&kd[r * 80 + ch * 8], kg + (size_t)(kc * 64 + r) * 1024 + ch * 8);
        }
        #pragma unroll
        for (int i = 0; i < 2; i++) {
            int idx = tid + i * 256;
            int r = idx >> 3, ch = idx & 7;
            cp16(&vd[r * 80 + ch * 8], vtb + (size_t)r * 1024 + kc * 64 + ch * 8);
        }
    };

    float acc[2][4][4];
    #pragma unroll
    for (int mi = 0; mi < 2; mi++)
        #pragma unroll
        for (int ni = 0; ni < 4; ni++)
            #pragma unroll
            for (int j = 0; j < 4; j++) acc[mi][ni][j] = 0.0f;

    ldKV(0);
    CP_COMMIT();

    for (int kc = 0; kc < 16; kc++) {
        if (kc + 1 < 16) { ldKV(kc + 1); CP_COMMIT(); CP_WAIT1(); }
        else CP_WAIT0();
        __syncthreads();    // K/V chunk ready; prev-iter ph reads done

        // ---- S chunk = Q @ K_chunk^T : 128 x 64, warp tile 32x32 ----
        const __half* kcur = kb + (kc & 1) * 5120;
        float sacc[2][4][4];
        #pragma unroll
        for (int mi = 0; mi < 2; mi++)
            #pragma unroll
            for (int ni = 0; ni < 4; ni++)
                #pragma unroll
                for (int j = 0; j < 4; j++) sacc[mi][ni][j] = 0.0f;
        #pragma unroll
        for (int k16 = 0; k16 < 4; k16++) {
            const int kx = (k16 << 4) + (qc << 2);
            unsigned ua[2][4], ub[4][2];
            #pragma unroll
            for (int mi = 0; mi < 2; mi++) {
                int r = wm * 32 + mi * 16 + qr;
                uint2 u0 = *(const uint2*)&qs[r * 80 + kx];
                uint2 u1 = *(const uint2*)&qs[(r + 8) * 80 + kx];
                ua[mi][0] = u0.x; ua[mi][1] = u1.x;
                ua[mi][2] = u0.y; ua[mi][3] = u1.y;
            }
            #pragma unroll
            for (int ni = 0; ni < 4; ni++) {
                int n = wn * 32 + ni * 8 + qr;
                uint2 v = *(const uint2*)&kcur[n * 80 + kx];
                ub[ni][0] = v.x; ub[ni][1] = v.y;
            }
            #pragma unroll
            for (int mi = 0; mi < 2; mi++)
                #pragma unroll
                for (int ni = 0; ni < 4; ni++)
                    mma_f16(sacc[mi][ni], ua[mi], ub[ni]);
        }

        // ---- normalize: probs (f32, natural) + P fp16 perm16 into ph ----
        #pragma unroll
        for (int mi = 0; mi < 2; mi++)
            #pragma unroll
            for (int ni = 0; ni < 4; ni++) {
                int col = wn * 32 + ni * 8 + (qc << 1);
                int slot = wn * 32 + ((ni & 2) << 3) + (qc << 2) + ((ni & 1) << 1);
                #pragma unroll
                for (int h2 = 0; h2 < 2; h2++) {
                    int r = wm * 32 + mi * 16 + qr + h2 * 8;
                    float inv = rinv[r];
                    float v0 = sacc[mi][ni][h2 * 2 + 0] * 0.125f;
                    float v1 = sacc[mi][ni][h2 * 2 + 1] * 0.125f;
                    float p0 = __expf(v0) * inv;
                    float p1 = __expf(v1) * inv;
                    *(float2*)&prb[(size_t)r * 1024 + kc * 64 + col] = make_float2(p0, p1);
                    *(unsigned*)&ph[r * 80 + slot] = packh(p0, p1);
                }
            }
        __syncthreads();    // ph complete before AV reads

        // ---- AV: acc += P_chunk @ V_chunk^T ----
        const __half* vcur = vb + (kc & 1) * 5120;
        #pragma unroll
        for (int k16 = 0; k16 < 4; k16++) {
            const int kx = (k16 << 4) + (qc << 2);
            unsigned ua[2][4], ub[4][2];
            #pragma unroll
            for (int mi = 0; mi < 2; mi++) {
                int r = wm * 32 + mi * 16 + qr;
                uint2 u0 = *(const uint2*)&ph[r * 80 + kx];
                uint2 u1 = *(const uint2*)&ph[(r + 8) * 80 + kx];
                ua[mi][0] = u0.x; ua[mi][1] = u1.x;
                ua[mi][2] = u0.y; ua[mi][3] = u1.y;
            }
            #pragma unroll
            for (int ni = 0; ni < 4; ni++) {
                int n = wn * 32 + ni * 8 + qr;
                uint2 v = *(const uint2*)&vcur[n * 80 + kx];
                ub[ni][0] = v.x; ub[ni][1] = v.y;
            }
            #pragma unroll
            for (int mi = 0; mi < 2; mi++)
                #pragma unroll
                for (int ni = 0; ni < 4; ni++)
                    mma_f16(acc[mi][ni], ua[mi], ub[ni]);
        }
        __syncthreads();    // AV reads done before next-iter ph writes
    }

    // epilogue -> ctx fp16 perm16
    #pragma unroll
    for (int mi = 0; mi < 2; mi++)
        #pragma unroll
        for (int g = 0; g < 2; g++) {
            int cg16 = h * 64 + wn * 32 + g * 16;
            #pragma unroll
            for (int h2 = 0; h2 < 2; h2++) {
                int r = m0 + wm * 32 + mi * 16 + qr + h2 * 8;
                uint2 pk;
                pk.x = packh(acc[mi][2 * g + 0][h2 * 2 + 0], acc[mi][2 * g + 0][h2 * 2 + 1]);
                pk.y = packh(acc[mi][2 * g + 1][h2 * 2 + 0], acc[mi][2 * g + 1][h2 * 2 + 1]);
                *(uint2*)&ctx[((size_t)(b * 1024 + r)) * 1024 + cg16 + (qc << 2)] = pk;
            }
        }
}

// ---------------- prep: [S,B,D] -> batch-first fp16 perm16 ----------------
__global__ void prep_kernel(const float* __restrict__ src, const float* __restrict__ pos,
                            __half* __restrict__ qkin, __half* __restrict__ srcbf)
{
    size_t idx = (size_t)blockIdx.x * blockDim.x + threadIdx.x;
    if (idx >= (size_t)S_ * B_ * D_) return;
    int d = (int)(idx % D_);
    size_t sb = idx / D_;
    int b = (int)(sb % B_);
    int s = (int)(sb / B_);
    int dp = (d & ~15) + inv16(d & 15);
    size_t o = ((size_t)(b * S_ + s)) * D_ + dp;
    float sv = src[idx];
    qkin[o]  = __float2half(sv + pos[idx]);
    srcbf[o] = __float2half(sv);
}

// ---------------- merged weight transpose+perm16 (all 6 weights, fp16) ------
__global__ void wprep(const float* __restrict__ Wq, const float* __restrict__ Wk,
                      const float* __restrict__ Wv, const float* __restrict__ Wo,
                      const float* __restrict__ W1, const float* __restrict__ W2,
                      __half* __restrict__ wr)
{
    __shared__ float t[32][33];
    int bid = blockIdx.x;
    const float* W; __half* Wt; int K, N, tt, nb;
    if (bid < 4096) {
        int w = bid >> 10; tt = bid & 1023; K = 1024; N = 1024; nb = 32;
        W = (w == 0) ? Wq : (w == 1) ? Wk : (w == 2) ? Wv : Wo;
        Wt = wr + (size_t)w * 1048576;
    } else if (bid < 8192) {
        tt = bid - 4096; K = 1024; N = 4096; nb = 128;
        W = W1; Wt = wr + 4194304;
    } else {
        tt = bid - 8192; K = 4096; N = 1024; nb = 32;
        W = W2; Wt = wr + 8388608;
    }
    int n0 = (tt % nb) * 32, k0 = (tt / nb) * 32;
    int tx = threadIdx.x, ty = threadIdx.y;
    #pragma unroll
    for (int i = 0; i < 32; i += 8)
        t[ty + i][tx] = W[(size_t)(k0 + ty + i) * N + n0 + tx];
    __syncthreads();
    #pragma unroll
    for (int i = 0; i < 32; i += 8) {
        int n = ty + i;
        int ks = (tx & ~15) + sig16(tx & 15);
        Wt[(size_t)(n0 + n) * K + k0 + tx] = __float2half(t[ks][n]);
    }
}

// ---------------- fused add + LayerNorm (+ optional fp16 perm16 copy) -------
__global__ void ln_kernel(const float* __restrict__ in1, int in1_sbd,
                          const float* __restrict__ in2,
                          const float* __restrict__ gamma, const float* __restrict__ beta,
                          float* __restrict__ out, int out_sbd,
                          __half* __restrict__ xp)
{
    int m = blockIdx.x;
    int b = m / S_, s = m % S_;
    size_t sbd_off = ((size_t)(s * B_ + b)) * D_;
    size_t bf_off  = (size_t)m * D_;
    const float* p1 = in1 + (in1_sbd ? sbd_off : bf_off);
    const float* p2 = in2 + bf_off;
    float* po = out + (out_sbd ? sbd_off : bf_off);

    __shared__ float xs[D_];
    __shared__ float r1[256], r2[256];
    int tid = threadIdx.x;
    float s1 = 0.0f, s2 = 0.0f;
    for (int d = tid; d < D_; d += 256) {
        float v = p1[d] + p2[d];
        xs[d] = v; s1 += v; s2 += v * v;
    }
    r1[tid] = s1; r2[tid] = s2;
    __syncthreads();
    for (int st = 128; st > 0; st >>= 1) {
        if (tid < st) { r1[tid] += r1[tid + st]; r2[tid] += r2[tid + st]; }
        __syncthreads();
    }
    float mean = r1[0] * (1.0f / D_);
    float var  = r2[0] * (1.0f / D_) - mean * mean;
    float rstd = rsqrtf(var + 1e-5f);
    for (int d = tid; d < D_; d += 256) {
        float v = (xs[d] - mean) * rstd * gamma[d] + beta[d];
        po[d] = v;
        if (xp) {
            int ds = (d & ~15) + sig16(d & 15);
            float vp = (xs[ds] - mean) * rstd * gamma[ds] + beta[ds];
            xp[bf_off + d] = __float2half(vp);
        }
    }
}

// ---------------- launch ----------------
extern "C" void kernel_launch(void* const* d_in, const int* in_sizes, int n_in,
                              void* d_out, int out_size)
{
    static __half *qkin = nullptr, *srcbf, *Qh, *Kh, *vt, *ctxh, *h1, *wr;
    static float *ao, *x, *f2, *psum, *attn_fb;
    if (!qkin) {
        cudaGetSymbolAddress((void**)&qkin,  g_qkin);
        cudaGetSymbolAddress((void**)&srcbf, g_srcbf);
        cudaGetSymbolAddress((void**)&Qh,    g_Q);
        cudaGetSymbolAddress((void**)&Kh,    g_K);
        cudaGetSymbolAddress((void**)&vt,    g_vt);
        cudaGetSymbolAddress((void**)&ctxh,  g_ctx);
        cudaGetSymbolAddress((void**)&h1,    g_h1);
        cudaGetSymbolAddress((void**)&wr,    g_wr);
        cudaGetSymbolAddress((void**)&ao,    g_ao);
        cudaGetSymbolAddress((void**)&x,     g_x);
        cudaGetSymbolAddress((void**)&f2,    g_f2);
        cudaGetSymbolAddress((void**)&psum,  g_psum);
        cudaGetSymbolAddress((void**)&attn_fb, g_attn_fb);
    }

    const float* src = (const float*)d_in[0];
    const float* pos = (const float*)d_in[1];
    const float* Wq  = (const float*)d_in[2];
    const float* bq  = (const float*)d_in[3];
    const float* Wk  = (const float*)d_in[4];
    const float* bk  = (const float*)d_in[5];
    const float* Wv  = (const float*)d_in[6];
    const float* bv  = (const float*)d_in[7];
    const float* Wo  = (const float*)d_in[8];
    const float* bo  = (const float*)d_in[9];
    const float* W1  = (const float*)d_in[10];
    const float* b1  = (const float*)d_in[11];
    const float* W2  = (const float*)d_in[12];
    const float* b2  = (const float*)d_in[13];
    const float* g1  = (const float*)d_in[14];
    const float* be1 = (const float*)d_in[15];
    const float* g2  = (const float*)d_in[16];
    const float* be2 = (const float*)d_in[17];

    float* out = (float*)d_out;
    long long need = (long long)S_ * B_ * D_ + (long long)B_ * H_ * S_ * S_;
    float* probs  = ((long long)out_size >= need) ? out + (size_t)S_ * B_ * D_ : attn_fb;

    const int SMT = 2 * 20480 * 2;                // 81920 B
    const int SMA = 40960 * 2 + 512;              // q+k+v+ph halfs + rinv = 82432 B
    cudaFuncSetAttribute(tgemm,      cudaFuncAttributeMaxDynamicSharedMemorySize, SMT);
    cudaFuncSetAttribute(attn_fused, cudaFuncAttributeMaxDynamicSharedMemorySize, SMA);

    __half* wqr = wr;
    __half* wkr = wr + 1048576;
    __half* wvr = wr + 2097152;
    __half* wor = wr + 3145728;
    __half* w1r = wr + 4194304;
    __half* w2r = wr + 8388608;

    // 1) prep
    wprep<<<12288, dim3(32, 8)>>>(Wq, Wk, Wv, Wo, W1, W2, wr);
    prep_kernel<<<32768, 256>>>(src, pos, qkin, srcbf);

    const long long SD = (long long)S_ * D_;
    const long long SS = (long long)S_ * S_;

    // 2-4) QKV projections: Q,K fp16 perm16; V -> transposed fp16 Vt
    tgemm<<<dim3(8, 64, 1), 256, SMT>>>(qkin, wqr, bq, nullptr, Qh, nullptr,
        1024, D_, D_, D_, 1, 0, 0, 0, 0, 0, 0, 1.0f, 0, 1);
    tgemm<<<dim3(8, 64, 1), 256, SMT>>>(qkin, wkr, bk, nullptr, Kh, nullptr,
        1024, D_, D_, D_, 1, 0, 0, 0, 0, 0, 0, 1.0f, 0, 1);
    tgemm<<<dim3(8, 64, 1), 256, SMT>>>(srcbf, wvr, bv, nullptr, vt, nullptr,
        1024, D_, D_, D_, 1, 0, 0, 0, 0, 0, 0, 1.0f, 0, 2);

    // 5) psum pass: scores recomputed later; only exp row-sum partials stored
    tgemm<<<dim3(8, 8, B_ * H_), 256, SMT>>>(Qh, Kh, nullptr, nullptr, nullptr, psum,
        64, D_, D_, S_, H_,
        SD, 64, SD, 64, (long long)H_ * SS, SS, 0.125f, 0, 0);

    // 6) fused attention: S recompute + softmax + probs + AV -> ctx fp16 perm16
    attn_fused<<<dim3(8, B_ * H_), 256, SMA>>>(Qh, Kh, vt, psum, probs, ctxh);

    // 7) output projection (f32 out)
    tgemm<<<dim3(8, 64, 1), 256, SMT>>>(ctxh, wor, bo, ao, nullptr, nullptr,
        1024, D_, D_, D_, 1, 0, 0, 0, 0, 0, 0, 1.0f, 0, 0);

    // 8) LN1: x f32 + xp fp16 perm16 (reuse Qh)
    __half* xp = Qh;
    ln_kernel<<<M_TOK, 256>>>(src, 1, ao, g1, be1, x, 0, xp);

    // 9-10) FFN
    tgemm<<<dim3(32, 64, 1), 256, SMT>>>(xp, w1r, b1, nullptr, h1, nullptr,
        1024, D_, D_, F_, 1, 0, 0, 0, 0, 0, 0, 1.0f, 1, 1);
    tgemm<<<dim3(8, 64, 1), 256, SMT>>>(h1, w2r, b2, f2, nullptr, nullptr,
        4096, F_, F_, D_, 1, 0, 0, 0, 0, 0, 0, 1.0f, 0, 0);

    // 11) LN2 -> out
    ln_kernel<<<M_TOK, 256>>>(x, 0, f2, g2, be2, out, 1, nullptr);
}

// round 15
// speedup vs baseline: 2.3548x; 1.0539x over previous
#include <cuda_runtime.h>
#include <cuda_fp16.h>
#include <math.h>
#include <stdint.h>

#define S_ 1024
#define B_ 8
#define D_ 1024
#define H_ 16
#define F_ 4096
#define M_TOK (S_*B_)

// ---------------- scratch ----------------
__device__ __half g_qkin[8388608];   // src+pos fp16 batch-first
__device__ __half g_srcbf[8388608];  // src fp16 batch-first
__device__ __half g_Q [8388608];     // Q fp16 (reused as xp after attention)
__device__ __half g_K [8388608];     // K fp16
__device__ __half g_vt[8388608];     // V transposed per head [B,H,64,S] fp16
__device__ __half g_ctx[8388608];    // ctx fp16
__device__ __half g_h1[33554432];    // h1 fp16
__device__ __half g_wr[12582912];    // W^T [n][k] fp16
__device__ float g_ao[8388608];
__device__ float g_x [8388608];
__device__ float g_f2[8388608];
__device__ float g_psum[4194304];    // exp row-sum partials [bh][32][1024]
__device__ float g_attn_fb[134217728];

__device__ __forceinline__ void cp16(void* s, const void* g) {
    unsigned sa = (unsigned)__cvta_generic_to_shared(s);
    asm volatile("cp.async.ca.shared.global [%0], [%1], 16;" :: "r"(sa), "l"(g));
}
#define CP_COMMIT() asm volatile("cp.async.commit_group;")
#define CP_WAIT0()  asm volatile("cp.async.wait_group 0;")
#define CP_WAIT1()  asm volatile("cp.async.wait_group 1;")

__device__ __forceinline__ void mma_f16(float* d, const unsigned* a, const unsigned* b) {
    asm volatile(
        "mma.sync.aligned.m16n8k16.row.col.f32.f16.f16.f32 "
        "{%0,%1,%2,%3}, {%4,%5,%6,%7}, {%8,%9}, {%0,%1,%2,%3};"
        : "+f"(d[0]), "+f"(d[1]), "+f"(d[2]), "+f"(d[3])
        : "r"(a[0]), "r"(a[1]), "r"(a[2]), "r"(a[3]), "r"(b[0]), "r"(b[1]));
}
__device__ __forceinline__ void ldm4(unsigned* r, unsigned a) {
    asm volatile("ldmatrix.sync.aligned.m8n8.x4.shared.b16 {%0,%1,%2,%3}, [%4];"
        : "=r"(r[0]), "=r"(r[1]), "=r"(r[2]), "=r"(r[3]) : "r"(a));
}
__device__ __forceinline__ unsigned packh(float a, float b) {
    __half2 t; t.x = __float2half(a); t.y = __float2half(b);
    return *(unsigned*)&t;
}
__device__ __forceinline__ unsigned smem_u32(const void* p) {
    return (unsigned)__cvta_generic_to_shared(p);
}

// Row stride in halfs: 72 (144 B) -> ldmatrix phases conflict-free.
#define RS 72

// ================== fp16 GEMM: 128x128 CTA tile, 8 warps (64x32 each) ==================
// A[m][k], B[n][k] fp16 natural order. BK=64, 2-stage cp.async, ldmatrix fragments.
// mode: 0 = f32 out (Cf may be null -> psum only), 1 = fp16 out, 2 = vt out.
__global__ void __launch_bounds__(256, 2) tgemm(
    const __half* __restrict__ A, const __half* __restrict__ Bm,
    const float* __restrict__ bias,
    float* __restrict__ Cf, __half* __restrict__ Ch, float* __restrict__ psum,
    int K, int lda, int ldb, int ldc, int zdiv,
    long long sAh, long long sAl, long long sBh, long long sBl,
    long long sCh, long long sCl,
    float alpha, int relu, int mode)
{
    extern __shared__ __half hsm[];      // 2 stages x (A 128xRS + B 128xRS)
    const unsigned su = smem_u32(hsm);
    const int tid = threadIdx.x;
    const int wid = tid >> 5, lane = tid & 31;
    const int wm = wid & 1, wn = wid >> 1;
    const int qr = lane >> 2, qc = lane & 3;
    const int m0 = blockIdx.y * 128;
    const int n0 = blockIdx.x * 128;
    const int z  = blockIdx.z;

    const __half* Ag = A + (long long)(z / zdiv) * sAh + (long long)(z % zdiv) * sAl
                         + (size_t)m0 * lda;
    const __half* Bg = Bm + (long long)(z / zdiv) * sBh + (long long)(z % zdiv) * sBl
                         + (size_t)n0 * ldb;
    float* Cg = Cf ? (Cf + (long long)(z / zdiv) * sCh + (long long)(z % zdiv) * sCl) : nullptr;

    const int STG = 2 * 128 * RS;        // halfs per stage (A+B)

    auto ld_stage = [&](int s, int k0) {
        __half* as = hsm + s * STG;
        __half* bs = as + 128 * RS;
        #pragma unroll
        for (int i = 0; i < 4; i++) {
            int idx = tid + i * 256;
            int r = idx >> 3, ch = idx & 7;
            cp16(&as[r * RS + ch * 8], Ag + (size_t)r * lda + k0 + ch * 8);
        }
        #pragma unroll
        for (int i = 0; i < 4; i++) {
            int idx = tid + i * 256;
            int r = idx >> 3, ch = idx & 7;
            cp16(&bs[r * RS + ch * 8], Bg + (size_t)r * ldb + k0 + ch * 8);
        }
    };

    // ldmatrix per-lane offsets (bytes)
    unsigned aoff[4], boff[2];
    {
        int arow = (lane & 15);
        int acol = (lane >> 4) << 3;
        #pragma unroll
        for (int mi = 0; mi < 4; mi++)
            aoff[mi] = ((wm * 64 + mi * 16 + arow) * RS + acol) * 2;
        int brow = (lane & 7) + ((lane >> 4) << 3);
        int bcol = (lane & 8) ? 8 : 0;
        #pragma unroll
        for (int g = 0; g < 2; g++)
            boff[g] = ((wn * 32 + g * 16 + brow) * RS + bcol) * 2 + 128 * RS * 2;
    }

    float acc[4][4][4];
    #pragma unroll
    for (int mi = 0; mi < 4; mi++)
        #pragma unroll
        for (int ni = 0; ni < 4; ni++)
            #pragma unroll
            for (int j = 0; j < 4; j++) acc[mi][ni][j] = 0.0f;

    const int nk = K >> 6;
    ld_stage(0, 0);
    CP_COMMIT();

    for (int kt = 0; kt < nk; kt++) {
        if (kt + 1 < nk) {
            ld_stage((kt + 1) & 1, (kt + 1) << 6);
            CP_COMMIT();
            CP_WAIT1();
        } else {
            CP_WAIT0();
        }
        __syncthreads();
        const unsigned sbase = su + (kt & 1) * STG * 2;

        #pragma unroll
        for (int k16 = 0; k16 < 4; k16++) {
            const unsigned kb2 = k16 * 32;       // 16 halfs
            unsigned ua[4][4], ub[2][4];
            #pragma unroll
            for (int mi = 0; mi < 4; mi++)
                ldm4(ua[mi], sbase + aoff[mi] + kb2);
            #pragma unroll
            for (int g = 0; g < 2; g++)
                ldm4(ub[g], sbase + boff[g] + kb2);
            #pragma unroll
            for (int mi = 0; mi < 4; mi++)
                #pragma unroll
                for (int ni = 0; ni < 4; ni++)
                    mma_f16(acc[mi][ni], ua[mi], &ub[ni >> 1][(ni & 1) << 1]);
        }
        __syncthreads();
    }

    if (mode == 2) {
        // V-transpose epilogue: acc -> smem f32 -> Vt[b][h][d][t] fp16
        float* fsm = (float*)hsm;                  // 128 x 132
        #pragma unroll
        for (int mi = 0; mi < 4; mi++)
            #pragma unroll
            for (int ni = 0; ni < 4; ni++) {
                int r = wm * 64 + mi * 16 + qr;
                int c = wn * 32 + ni * 8 + (qc << 1);
                #pragma unroll
                for (int h2 = 0; h2 < 2; h2++) {
                    fsm[(r + h2 * 8) * 132 + c]     = acc[mi][ni][h2 * 2 + 0] + bias[n0 + c];
                    fsm[(r + h2 * 8) * 132 + c + 1] = acc[mi][ni][h2 * 2 + 1] + bias[n0 + c + 1];
                }
            }
        __syncthreads();
        int b = m0 >> 10, t0 = m0 & 1023;
        for (int i = 0; i < 32; i++) {
            int idx = tid + i * 256;
            int c = idx >> 6, tp = idx & 63;
            int t = tp * 2;
            int gc = n0 + c, h = gc >> 6, d = gc & 63;
            float v0 = fsm[t * 132 + c];
            float v1 = fsm[(t + 1) * 132 + c];
            *(unsigned*)&Ch[(((size_t)(b * H_ + h)) * 64 + d) * 1024 + t0 + t] = packh(v0, v1);
        }
        return;
    }

    float es[4][2];
    #pragma unroll
    for (int mi = 0; mi < 4; mi++) { es[mi][0] = 0.0f; es[mi][1] = 0.0f; }

    if (mode == 1) {
        #pragma unroll
        for (int mi = 0; mi < 4; mi++)
            #pragma unroll
            for (int ni = 0; ni < 4; ni++) {
                int c0 = n0 + wn * 32 + ni * 8 + (qc << 1);
                float b0 = bias[c0], b1 = bias[c0 + 1];
                #pragma unroll
                for (int h2 = 0; h2 < 2; h2++) {
                    int row = m0 + wm * 64 + mi * 16 + qr + h2 * 8;
                    float v0 = acc[mi][ni][h2 * 2 + 0] + b0;
                    float v1 = acc[mi][ni][h2 * 2 + 1] + b1;
                    if (relu) { v0 = fmaxf(v0, 0.f); v1 = fmaxf(v1, 0.f); }
                    *(unsigned*)&Ch[(size_t)row * ldc + c0] = packh(v0, v1);
                }
            }
    } else {
        #pragma unroll
        for (int mi = 0; mi < 4; mi++)
            #pragma unroll
            for (int ni = 0; ni < 4; ni++) {
                int c0 = n0 + wn * 32 + ni * 8 + (qc << 1);
                float b0 = 0.0f, b1 = 0.0f;
                if (bias) { b0 = bias[c0]; b1 = bias[c0 + 1]; }
                #pragma unroll
                for (int h2 = 0; h2 < 2; h2++) {
                    int row = m0 + wm * 64 + mi * 16 + qr + h2 * 8;
                    float v0 = fmaf(acc[mi][ni][h2 * 2 + 0], alpha, b0);
                    float v1 = fmaf(acc[mi][ni][h2 * 2 + 1], alpha, b1);
                    if (relu) { v0 = fmaxf(v0, 0.f); v1 = fmaxf(v1, 0.f); }
                    if (psum) es[mi][h2] += __expf(v0) + __expf(v1);
                    if (Cg)
                        *(float2*)(Cg + (size_t)row * ldc + c0) = make_float2(v0, v1);
                }
            }
        if (psum) {
            int chunk = blockIdx.x * 4 + wn;
            #pragma unroll
            for (int mi = 0; mi < 4; mi++)
                #pragma unroll
                for (int h2 = 0; h2 < 2; h2++) {
                    float e = es[mi][h2];
                    e += __shfl_xor_sync(0xffffffffu, e, 1);
                    e += __shfl_xor_sync(0xffffffffu, e, 2);
                    if (qc == 0) {
                        int row = m0 + wm * 64 + mi * 16 + qr + h2 * 8;
                        psum[((size_t)z * 32 + chunk) * 1024 + row] = e;
                    }
                }
        }
    }
}

// ================== fully fused attention (ldmatrix fragments) ==================
__global__ void __launch_bounds__(256, 2) attn_fused(
    const __half* __restrict__ Qh, const __half* __restrict__ Kh,
    const __half* __restrict__ Vt, const float* __restrict__ psum,
    float* __restrict__ probs, __half* __restrict__ ctx)
{
    extern __shared__ __half hsm[];
    // halfs: qs[128*RS] @0, kb 2x[64*RS] @9216, vb 2x[64*RS] @18432, ph[128*RS] @27648
    __half* qs = hsm;
    __half* kb = hsm + 128 * RS;
    __half* vb = hsm + 128 * RS + 2 * 64 * RS;
    __half* ph = hsm + 128 * RS + 4 * 64 * RS;
    float* rinv = (float*)(hsm + 2 * 128 * RS + 4 * 64 * RS);

    const unsigned su = smem_u32(hsm);
    const int tid = threadIdx.x;
    const int w = tid >> 5, lane = tid & 31;
    const int wm = w & 3, wn = w >> 2;            // 4 m x 2 n (32x32 tiles)
    const int qr = lane >> 2, qc = lane & 3;
    const int bh = blockIdx.y, b = bh >> 4, h = bh & 15;
    const int m0 = blockIdx.x * 128;
    float* prb = probs + ((size_t)bh << 20) + (size_t)m0 * 1024;
    const __half* qg = Qh + ((size_t)(b * 1024 + m0)) * 1024 + h * 64;
    const __half* kg = Kh + ((size_t)(b * 1024)) * 1024 + h * 64;
    const __half* vtb = Vt + ((size_t)bh << 16);  // [64][1024]

    {   // row sums from psum partials
        int row = tid >> 1, half = tid & 1;
        const float* pp = psum + ((size_t)bh * 32) * 1024 + m0 + row;
        float s = 0.0f;
        #pragma unroll
        for (int c = 0; c < 16; c++) s += pp[(half * 16 + c) * 1024];
        s += __shfl_xor_sync(0xffffffffu, s, 1);
        if (half == 0) rinv[row] = 1.0f / s;
    }

    // load Q tile [128][64]
    #pragma unroll
    for (int i = 0; i < 4; i++) {
        int idx = tid + i * 256;
        int r = idx >> 3, ch = idx & 7;
        cp16(&qs[r * RS + ch * 8], qg + (size_t)r * 1024 + ch * 8);
    }

    auto ldKV = [&](int kc) {
        __half* kd = kb + (kc & 1) * 64 * RS;
        __half* vd = vb + (kc & 1) * 64 * RS;
        #pragma unroll
        for (int i = 0; i < 2; i++) {
            int idx = tid + i * 256;
            int r = idx >> 3, ch = idx & 7;
            cp16(&kd[r * RS + ch * 8], kg + (size_t)(kc * 64 + r) * 1024 + ch * 8);
        }
        #pragma unroll
        for (int i = 0; i < 2; i++) {
            int idx = tid + i * 256;
            int r = idx >> 3, ch = idx & 7;
            cp16(&vd[r * RS + ch * 8], vtb + (size_t)r * 1024 + kc * 64 + ch * 8);
        }
    };

    // ldmatrix offsets (bytes)
    unsigned qoff[2], phoff[2], bo[2];
    {
        int arow = (lane & 15);
        int acol = (lane >> 4) << 3;
        #pragma unroll
        for (int mi = 0; mi < 2; mi++) {
            qoff[mi]  = ((wm * 32 + mi * 16 + arow) * RS + acol) * 2;
            phoff[mi] = qoff[mi] + (128 * RS + 4 * 64 * RS) * 2;
        }
        int brow = (lane & 7) + ((lane >> 4) << 3);
        int bcol = (lane & 8) ? 8 : 0;
        #pragma unroll
        for (int g = 0; g < 2; g++)
            bo[g] = ((wn * 32 + g * 16 + brow) * RS + bcol) * 2;
    }
    const unsigned kbase0 = su + (128 * RS) * 2;
    const unsigned vbase0 = su + (128 * RS + 2 * 64 * RS) * 2;

    float acc[2][4][4];
    #pragma unroll
    for (int mi = 0; mi < 2; mi++)
        #pragma unroll
        for (int ni = 0; ni < 4; ni++)
            #pragma unroll
            for (int j = 0; j < 4; j++) acc[mi][ni][j] = 0.0f;

    ldKV(0);
    CP_COMMIT();

    for (int kc = 0; kc < 16; kc++) {
        if (kc + 1 < 16) { ldKV(kc + 1); CP_COMMIT(); CP_WAIT1(); }
        else CP_WAIT0();
        __syncthreads();

        // ---- S chunk = Q @ K_chunk^T ----
        const unsigned kbase = kbase0 + (kc & 1) * (64 * RS) * 2;
        float sacc[2][4][4];
        #pragma unroll
        for (int mi = 0; mi < 2; mi++)
            #pragma unroll
            for (int ni = 0; ni < 4; ni++)
                #pragma unroll
                for (int j = 0; j < 4; j++) sacc[mi][ni][j] = 0.0f;
        #pragma unroll
        for (int k16 = 0; k16 < 4; k16++) {
            const unsigned kb2 = k16 * 32;
            unsigned ua[2][4], ub[2][4];
            #pragma unroll
            for (int mi = 0; mi < 2; mi++)
                ldm4(ua[mi], su + qoff[mi] + kb2);
            #pragma unroll
            for (int g = 0; g < 2; g++)
                ldm4(ub[g], kbase + bo[g] + kb2);
            #pragma unroll
            for (int mi = 0; mi < 2; mi++)
                #pragma unroll
                for (int ni = 0; ni < 4; ni++)
                    mma_f16(sacc[mi][ni], ua[mi], &ub[ni >> 1][(ni & 1) << 1]);
        }

        // ---- normalize: probs (f32) + P fp16 into ph ----
        #pragma unroll
        for (int mi = 0; mi < 2; mi++)
            #pragma unroll
            for (int ni = 0; ni < 4; ni++) {
                int col = wn * 32 + ni * 8 + (qc << 1);
                #pragma unroll
                for (int h2 = 0; h2 < 2; h2++) {
                    int r = wm * 32 + mi * 16 + qr + h2 * 8;
                    float inv = rinv[r];
                    float v0 = sacc[mi][ni][h2 * 2 + 0] * 0.125f;
                    float v1 = sacc[mi][ni][h2 * 2 + 1] * 0.125f;
                    float p0 = __expf(v0) * inv;
                    float p1 = __expf(v1) * inv;
                    *(float2*)&prb[(size_t)r * 1024 + kc * 64 + col] = make_float2(p0, p1);
                    *(unsigned*)&ph[r * RS + col] = packh(p0, p1);
                }
            }
        __syncthreads();

        // ---- AV: acc += P_chunk @ V_chunk^T ----
        const unsigned vbase = vbase0 + (kc & 1) * (64 * RS) * 2;
        #pragma unroll
        for (int k16 = 0; k16 < 4; k16++) {
            const unsigned kb2 = k16 * 32;
            unsigned ua[2][4], ub[2][4];
            #pragma unroll
            for (int mi = 0; mi < 2; mi++)
                ldm4(ua[mi], su + phoff[mi] + kb2);
            #pragma unroll
            for (int g = 0; g < 2; g++)
                ldm4(ub[g], vbase + bo[g] + kb2);
            #pragma unroll
            for (int mi = 0; mi < 2; mi++)
                #pragma unroll
                for (int ni = 0; ni < 4; ni++)
                    mma_f16(acc[mi][ni], ua[mi], &ub[ni >> 1][(ni & 1) << 1]);
        }
        __syncthreads();
    }

    // epilogue -> ctx fp16 (natural)
    #pragma unroll
    for (int mi = 0; mi < 2; mi++)
        #pragma unroll
        for (int ni = 0; ni < 4; ni++) {
            int c0 = h * 64 + wn * 32 + ni * 8 + (qc << 1);
            #pragma unroll
            for (int h2 = 0; h2 < 2; h2++) {
                int r = m0 + wm * 32 + mi * 16 + qr + h2 * 8;
                *(unsigned*)&ctx[((size_t)(b * 1024 + r)) * 1024 + c0] =
                    packh(acc[mi][ni][h2 * 2 + 0], acc[mi][ni][h2 * 2 + 1]);
            }
        }
}

// ---------------- prep: [S,B,D] -> batch-first fp16 ----------------
__global__ void prep_kernel(const float* __restrict__ src, const float* __restrict__ pos,
                            __half* __restrict__ qkin, __half* __restrict__ srcbf)
{
    size_t idx = (size_t)blockIdx.x * blockDim.x + threadIdx.x;
    if (idx >= (size_t)S_ * B_ * D_) return;
    int d = (int)(idx % D_);
    size_t sb = idx / D_;
    int b = (int)(sb % B_);
    int s = (int)(sb / B_);
    size_t o = ((size_t)(b * S_ + s)) * D_ + d;
    float sv = src[idx];
    qkin[o]  = __float2half(sv + pos[idx]);
    srcbf[o] = __float2half(sv);
}

// ---------------- merged weight transpose (all 6 weights, fp16) ------
__global__ void wprep(const float* __restrict__ Wq, const float* __restrict__ Wk,
                      const float* __restrict__ Wv, const float* __restrict__ Wo,
                      const float* __restrict__ W1, const float* __restrict__ W2,
                      __half* __restrict__ wr)
{
    __shared__ float t[32][33];
    int bid = blockIdx.x;
    const float* W; __half* Wt; int K, N, tt, nb;
    if (bid < 4096) {
        int w = bid >> 10; tt = bid & 1023; K = 1024; N = 1024; nb = 32;
        W = (w == 0) ? Wq : (w == 1) ? Wk : (w == 2) ? Wv : Wo;
        Wt = wr + (size_t)w * 1048576;
    } else if (bid < 8192) {
        tt = bid - 4096; K = 1024; N = 4096; nb = 128;
        W = W1; Wt = wr + 4194304;
    } else {
        tt = bid - 8192; K = 4096; N = 1024; nb = 32;
        W = W2; Wt = wr + 8388608;
    }
    int n0 = (tt % nb) * 32, k0 = (tt / nb) * 32;
    int tx = threadIdx.x, ty = threadIdx.y;
    #pragma unroll
    for (int i = 0; i < 32; i += 8)
        t[ty + i][tx] = W[(size_t)(k0 + ty + i) * N + n0 + tx];
    __syncthreads();
    #pragma unroll
    for (int i = 0; i < 32; i += 8) {
        int n = ty + i;
        Wt[(size_t)(n0 + n) * K + k0 + tx] = __float2half(t[tx][n]);
    }
}

// ---------------- fused add + LayerNorm (+ optional fp16 copy) -------
__global__ void ln_kernel(const float* __restrict__ in1, int in1_sbd,
                          const float* __restrict__ in2,
                          const float* __restrict__ gamma, const float* __restrict__ beta,
                          float* __restrict__ out, int out_sbd,
                          __half* __restrict__ xp)
{
    int m = blockIdx.x;
    int b = m / S_, s = m % S_;
    size_t sbd_off = ((size_t)(s * B_ + b)) * D_;
    size_t bf_off  = (size_t)m * D_;
    const float* p1 = in1 + (in1_sbd ? sbd_off : bf_off);
    const float* p2 = in2 + bf_off;
    float* po = out + (out_sbd ? sbd_off : bf_off);

    __shared__ float xs[D_];
    __shared__ float r1[256], r2[256];
    int tid = threadIdx.x;
    float s1 = 0.0f, s2 = 0.0f;
    for (int d = tid; d < D_; d += 256) {
        float v = p1[d] + p2[d];
        xs[d] = v; s1 += v; s2 += v * v;
    }
    r1[tid] = s1; r2[tid] = s2;
    __syncthreads();
    for (int st = 128; st > 0; st >>= 1) {
        if (tid < st) { r1[tid] += r1[tid + st]; r2[tid] += r2[tid + st]; }
        __syncthreads();
    }
    float mean = r1[0] * (1.0f / D_);
    float var  = r2[0] * (1.0f / D_) - mean * mean;
    float rstd = rsqrtf(var + 1e-5f);
    for (int d = tid; d < D_; d += 256) {
        float v = (xs[d] - mean) * rstd * gamma[d] + beta[d];
        po[d] = v;
        if (xp) xp[bf_off + d] = __float2half(v);
    }
}

// ---------------- launch ----------------
extern "C" void kernel_launch(void* const* d_in, const int* in_sizes, int n_in,
                              void* d_out, int out_size)
{
    static __half *qkin = nullptr, *srcbf, *Qh, *Kh, *vt, *ctxh, *h1, *wr;
    static float *ao, *x, *f2, *psum, *attn_fb;
    if (!qkin) {
        cudaGetSymbolAddress((void**)&qkin,  g_qkin);
        cudaGetSymbolAddress((void**)&srcbf, g_srcbf);
        cudaGetSymbolAddress((void**)&Qh,    g_Q);
        cudaGetSymbolAddress((void**)&Kh,    g_K);
        cudaGetSymbolAddress((void**)&vt,    g_vt);
        cudaGetSymbolAddress((void**)&ctxh,  g_ctx);
        cudaGetSymbolAddress((void**)&h1,    g_h1);
        cudaGetSymbolAddress((void**)&wr,    g_wr);
        cudaGetSymbolAddress((void**)&ao,    g_ao);
        cudaGetSymbolAddress((void**)&x,     g_x);
        cudaGetSymbolAddress((void**)&f2,    g_f2);
        cudaGetSymbolAddress((void**)&psum,  g_psum);
        cudaGetSymbolAddress((void**)&attn_fb, g_attn_fb);
    }

    const float* src = (const float*)d_in[0];
    const float* pos = (const float*)d_in[1];
    const float* Wq  = (const float*)d_in[2];
    const float* bq  = (const float*)d_in[3];
    const float* Wk  = (const float*)d_in[4];
    const float* bk  = (const float*)d_in[5];
    const float* Wv  = (const float*)d_in[6];
    const float* bv  = (const float*)d_in[7];
    const float* Wo  = (const float*)d_in[8];
    const float* bo  = (const float*)d_in[9];
    const float* W1  = (const float*)d_in[10];
    const float* b1  = (const float*)d_in[11];
    const float* W2  = (const float*)d_in[12];
    const float* b2  = (const float*)d_in[13];
    const float* g1  = (const float*)d_in[14];
    const float* be1 = (const float*)d_in[15];
    const float* g2  = (const float*)d_in[16];
    const float* be2 = (const float*)d_in[17];

    float* out = (float*)d_out;
    long long need = (long long)S_ * B_ * D_ + (long long)B_ * H_ * S_ * S_;
    float* probs  = ((long long)out_size >= need) ? out + (size_t)S_ * B_ * D_ : attn_fb;

    const int SMT = 2 * (2 * 128 * RS) * 2;               // 73728 B
    const int SMA = (2 * 128 * RS + 4 * 64 * RS) * 2 + 512; // 74240 B
    cudaFuncSetAttribute(tgemm,      cudaFuncAttributeMaxDynamicSharedMemorySize, SMT);
    cudaFuncSetAttribute(attn_fused, cudaFuncAttributeMaxDynamicSharedMemorySize, SMA);

    __half* wqr = wr;
    __half* wkr = wr + 1048576;
    __half* wvr = wr + 2097152;
    __half* wor = wr + 3145728;
    __half* w1r = wr + 4194304;
    __half* w2r = wr + 8388608;

    // 1) prep
    wprep<<<12288, dim3(32, 8)>>>(Wq, Wk, Wv, Wo, W1, W2, wr);
    prep_kernel<<<32768, 256>>>(src, pos, qkin, srcbf);

    const long long SD = (long long)S_ * D_;
    const long long SS = (long long)S_ * S_;

    // 2-4) QKV projections: Q,K fp16; V -> transposed fp16 Vt
    tgemm<<<dim3(8, 64, 1), 256, SMT>>>(qkin, wqr, bq, nullptr, Qh, nullptr,
        1024, D_, D_, D_, 1, 0, 0, 0, 0, 0, 0, 1.0f, 0, 1);
    tgemm<<<dim3(8, 64, 1), 256, SMT>>>(qkin, wkr, bk, nullptr, Kh, nullptr,
        1024, D_, D_, D_, 1, 0, 0, 0, 0, 0, 0, 1.0f, 0, 1);
    tgemm<<<dim3(8, 64, 1), 256, SMT>>>(srcbf, wvr, bv, nullptr, vt, nullptr,
        1024, D_, D_, D_, 1, 0, 0, 0, 0, 0, 0, 1.0f, 0, 2);

    // 5) psum pass: only exp row-sum partials stored
    tgemm<<<dim3(8, 8, B_ * H_), 256, SMT>>>(Qh, Kh, nullptr, nullptr, nullptr, psum,
        64, D_, D_, S_, H_,
        SD, 64, SD, 64, (long long)H_ * SS, SS, 0.125f, 0, 0);

    // 6) fused attention
    attn_fused<<<dim3(8, B_ * H_), 256, SMA>>>(Qh, Kh, vt, psum, probs, ctxh);

    // 7) output projection (f32 out)
    tgemm<<<dim3(8, 64, 1), 256, SMT>>>(ctxh, wor, bo, ao, nullptr, nullptr,
        1024, D_, D_, D_, 1, 0, 0, 0, 0, 0, 0, 1.0f, 0, 0);

    // 8) LN1: x f32 + xp fp16 (reuse Qh)
    __half* xp = Qh;
    ln_kernel<<<M_TOK, 256>>>(src, 1, ao, g1, be1, x, 0, xp);

    // 9-10) FFN
    tgemm<<<dim3(32, 64, 1), 256, SMT>>>(xp, w1r, b1, nullptr, h1, nullptr,
        1024, D_, D_, F_, 1, 0, 0, 0, 0, 0, 0, 1.0f, 1, 1);
    tgemm<<<dim3(8, 64, 1), 256, SMT>>>(h1, w2r, b2, f2, nullptr, nullptr,
        4096, F_, F_, D_, 1, 0, 0, 0, 0, 0, 0, 1.0f, 0, 0);

    // 11) LN2 -> out
    ln_kernel<<<M_TOK, 256>>>(x, 0, f2, g2, be2, out, 1, nullptr);
}

// round 16
// speedup vs baseline: 2.3660x; 1.0048x over previous
#include <cuda_runtime.h>
#include <cuda_fp16.h>
#include <math.h>
#include <stdint.h>

#define S_ 1024
#define B_ 8
#define D_ 1024
#define H_ 16
#define F_ 4096
#define M_TOK (S_*B_)

// ---------------- scratch ----------------
__device__ __half g_qkin[8388608];   // src+pos fp16 batch-first
__device__ __half g_srcbf[8388608];  // src fp16 batch-first
__device__ __half g_Q [8388608];     // Q fp16 (reused as xp after attention)
__device__ __half g_K [8388608];     // K fp16
__device__ __half g_vt[8388608];     // V transposed per head [B,H,64,S] fp16
__device__ __half g_ctx[8388608];    // ctx fp16
__device__ __half g_h1[33554432];    // h1 fp16
__device__ __half g_wr[12582912];    // W^T [n][k] fp16
__device__ float g_ao[8388608];
__device__ float g_x [8388608];
__device__ float g_f2[8388608];
__device__ float g_psum[4194304];    // exp row-sum partials [bh][32][1024]
__device__ float g_attn_fb[134217728];

__device__ __forceinline__ void cp16(void* s, const void* g) {
    unsigned sa = (unsigned)__cvta_generic_to_shared(s);
    asm volatile("cp.async.ca.shared.global [%0], [%1], 16;" :: "r"(sa), "l"(g));
}
#define CP_COMMIT() asm volatile("cp.async.commit_group;")
#define CP_WAIT0()  asm volatile("cp.async.wait_group 0;")
#define CP_WAIT1()  asm volatile("cp.async.wait_group 1;")

__device__ __forceinline__ void mma_f16(float* d, const unsigned* a, const unsigned* b) {
    asm volatile(
        "mma.sync.aligned.m16n8k16.row.col.f32.f16.f16.f32 "
        "{%0,%1,%2,%3}, {%4,%5,%6,%7}, {%8,%9}, {%0,%1,%2,%3};"
        : "+f"(d[0]), "+f"(d[1]), "+f"(d[2]), "+f"(d[3])
        : "r"(a[0]), "r"(a[1]), "r"(a[2]), "r"(a[3]), "r"(b[0]), "r"(b[1]));
}
__device__ __forceinline__ void ldm4(unsigned* r, unsigned a) {
    asm volatile("ldmatrix.sync.aligned.m8n8.x4.shared.b16 {%0,%1,%2,%3}, [%4];"
        : "=r"(r[0]), "=r"(r[1]), "=r"(r[2]), "=r"(r[3]) : "r"(a));
}
__device__ __forceinline__ unsigned packh(float a, float b) {
    __half2 t; t.x = __float2half(a); t.y = __float2half(b);
    return *(unsigned*)&t;
}
__device__ __forceinline__ unsigned smem_u32(const void* p) {
    return (unsigned)__cvta_generic_to_shared(p);
}

// Row stride in halfs: 72 (144 B) -> ldmatrix phases conflict-free.
#define RS 72

// ================== fp16 GEMM: 128x128 CTA tile, 4 warps (64x64 each) ==================
// A[m][k], B[n][k] fp16 natural order. BK=64, 2-stage cp.async, ldmatrix fragments.
// Warp grid 2x2; per k16: 8 LDSM.x4 feed 32 MMAs (smem-traffic optimal).
// mode: 0 = f32 out (Cf may be null -> psum only), 1 = fp16 out, 2 = vt out.
__global__ void __launch_bounds__(128, 2) tgemm(
    const __half* __restrict__ A, const __half* __restrict__ Bm,
    const float* __restrict__ bias,
    float* __restrict__ Cf, __half* __restrict__ Ch, float* __restrict__ psum,
    int K, int lda, int ldb, int ldc, int zdiv,
    long long sAh, long long sAl, long long sBh, long long sBl,
    long long sCh, long long sCl,
    float alpha, int relu, int mode)
{
    extern __shared__ __half hsm[];      // 2 stages x (A 128xRS + B 128xRS)
    const unsigned su = smem_u32(hsm);
    const int tid = threadIdx.x;
    const int wid = tid >> 5, lane = tid & 31;
    const int wm = wid & 1, wn = wid >> 1;      // 2 x 2 warps
    const int qr = lane >> 2, qc = lane & 3;
    const int m0 = blockIdx.y * 128;
    const int n0 = blockIdx.x * 128;
    const int z  = blockIdx.z;

    const __half* Ag = A + (long long)(z / zdiv) * sAh + (long long)(z % zdiv) * sAl
                         + (size_t)m0 * lda;
    const __half* Bg = Bm + (long long)(z / zdiv) * sBh + (long long)(z % zdiv) * sBl
                         + (size_t)n0 * ldb;
    float* Cg = Cf ? (Cf + (long long)(z / zdiv) * sCh + (long long)(z % zdiv) * sCl) : nullptr;

    const int STG = 2 * 128 * RS;        // halfs per stage (A+B)

    auto ld_stage = [&](int s, int k0) {
        __half* as = hsm + s * STG;
        __half* bs = as + 128 * RS;
        #pragma unroll
        for (int i = 0; i < 8; i++) {
            int idx = tid + i * 128;
            int r = idx >> 3, ch = idx & 7;
            cp16(&as[r * RS + ch * 8], Ag + (size_t)r * lda + k0 + ch * 8);
        }
        #pragma unroll
        for (int i = 0; i < 8; i++) {
            int idx = tid + i * 128;
            int r = idx >> 3, ch = idx & 7;
            cp16(&bs[r * RS + ch * 8], Bg + (size_t)r * ldb + k0 + ch * 8);
        }
    };

    // ldmatrix per-lane offsets (bytes)
    unsigned aoff[4], boff[4];
    {
        int arow = (lane & 15);
        int acol = (lane >> 4) << 3;
        #pragma unroll
        for (int mi = 0; mi < 4; mi++)
            aoff[mi] = ((wm * 64 + mi * 16 + arow) * RS + acol) * 2;
        int brow = (lane & 7) + ((lane >> 4) << 3);
        int bcol = (lane & 8) ? 8 : 0;
        #pragma unroll
        for (int g = 0; g < 4; g++)
            boff[g] = ((wn * 64 + g * 16 + brow) * RS + bcol) * 2 + 128 * RS * 2;
    }

    float acc[4][8][4];
    #pragma unroll
    for (int mi = 0; mi < 4; mi++)
        #pragma unroll
        for (int ni = 0; ni < 8; ni++)
            #pragma unroll
            for (int j = 0; j < 4; j++) acc[mi][ni][j] = 0.0f;

    const int nk = K >> 6;
    ld_stage(0, 0);
    CP_COMMIT();

    for (int kt = 0; kt < nk; kt++) {
        if (kt + 1 < nk) {
            ld_stage((kt + 1) & 1, (kt + 1) << 6);
            CP_COMMIT();
            CP_WAIT1();
        } else {
            CP_WAIT0();
        }
        __syncthreads();
        const unsigned sbase = su + (kt & 1) * STG * 2;

        #pragma unroll
        for (int k16 = 0; k16 < 4; k16++) {
            const unsigned kb2 = k16 * 32;       // 16 halfs
            unsigned ua[4][4], ub[4][4];
            #pragma unroll
            for (int mi = 0; mi < 4; mi++)
                ldm4(ua[mi], sbase + aoff[mi] + kb2);
            #pragma unroll
            for (int g = 0; g < 4; g++)
                ldm4(ub[g], sbase + boff[g] + kb2);
            #pragma unroll
            for (int mi = 0; mi < 4; mi++)
                #pragma unroll
                for (int ni = 0; ni < 8; ni++)
                    mma_f16(acc[mi][ni], ua[mi], &ub[ni >> 1][(ni & 1) << 1]);
        }
        __syncthreads();
    }

    if (mode == 2) {
        // V-transpose epilogue: acc -> smem f32 -> Vt[b][h][d][t] fp16
        float* fsm = (float*)hsm;                  // 128 x 132
        #pragma unroll
        for (int mi = 0; mi < 4; mi++)
            #pragma unroll
            for (int ni = 0; ni < 8; ni++) {
                int r = wm * 64 + mi * 16 + qr;
                int c = wn * 64 + ni * 8 + (qc << 1);
                #pragma unroll
                for (int h2 = 0; h2 < 2; h2++) {
                    fsm[(r + h2 * 8) * 132 + c]     = acc[mi][ni][h2 * 2 + 0] + bias[n0 + c];
                    fsm[(r + h2 * 8) * 132 + c + 1] = acc[mi][ni][h2 * 2 + 1] + bias[n0 + c + 1];
                }
            }
        __syncthreads();
        int b = m0 >> 10, t0 = m0 & 1023;
        for (int i = 0; i < 64; i++) {
            int idx = tid + i * 128;               // 8192 = 128 cols x 64 t-pairs
            int c = idx >> 6, tp = idx & 63;
            int t = tp * 2;
            int gc = n0 + c, h = gc >> 6, d = gc & 63;
            float v0 = fsm[t * 132 + c];
            float v1 = fsm[(t + 1) * 132 + c];
            *(unsigned*)&Ch[(((size_t)(b * H_ + h)) * 64 + d) * 1024 + t0 + t] = packh(v0, v1);
        }
        return;
    }

    if (mode == 1) {
        #pragma unroll
        for (int mi = 0; mi < 4; mi++)
            #pragma unroll
            for (int ni = 0; ni < 8; ni++) {
                int c0 = n0 + wn * 64 + ni * 8 + (qc << 1);
                float b0 = bias[c0], b1 = bias[c0 + 1];
                #pragma unroll
                for (int h2 = 0; h2 < 2; h2++) {
                    int row = m0 + wm * 64 + mi * 16 + qr + h2 * 8;
                    float v0 = acc[mi][ni][h2 * 2 + 0] + b0;
                    float v1 = acc[mi][ni][h2 * 2 + 1] + b1;
                    if (relu) { v0 = fmaxf(v0, 0.f); v1 = fmaxf(v1, 0.f); }
                    *(unsigned*)&Ch[(size_t)row * ldc + c0] = packh(v0, v1);
                }
            }
    } else {
        float es[4][2][2];                         // [mi][n-half(32col)][h2]
        #pragma unroll
        for (int mi = 0; mi < 4; mi++)
            #pragma unroll
            for (int nh = 0; nh < 2; nh++) { es[mi][nh][0] = 0.0f; es[mi][nh][1] = 0.0f; }

        #pragma unroll
        for (int mi = 0; mi < 4; mi++)
            #pragma unroll
            for (int ni = 0; ni < 8; ni++) {
                int c0 = n0 + wn * 64 + ni * 8 + (qc << 1);
                float b0 = 0.0f, b1 = 0.0f;
                if (bias) { b0 = bias[c0]; b1 = bias[c0 + 1]; }
                #pragma unroll
                for (int h2 = 0; h2 < 2; h2++) {
                    int row = m0 + wm * 64 + mi * 16 + qr + h2 * 8;
                    float v0 = fmaf(acc[mi][ni][h2 * 2 + 0], alpha, b0);
                    float v1 = fmaf(acc[mi][ni][h2 * 2 + 1], alpha, b1);
                    if (relu) { v0 = fmaxf(v0, 0.f); v1 = fmaxf(v1, 0.f); }
                    if (psum) es[mi][ni >> 2][h2] += __expf(v0) + __expf(v1);
                    if (Cg)
                        *(float2*)(Cg + (size_t)row * ldc + c0) = make_float2(v0, v1);
                }
            }
        if (psum) {
            #pragma unroll
            for (int mi = 0; mi < 4; mi++)
                #pragma unroll
                for (int nh = 0; nh < 2; nh++) {
                    int chunk = blockIdx.x * 4 + wn * 2 + nh;
                    #pragma unroll
                    for (int h2 = 0; h2 < 2; h2++) {
                        float e = es[mi][nh][h2];
                        e += __shfl_xor_sync(0xffffffffu, e, 1);
                        e += __shfl_xor_sync(0xffffffffu, e, 2);
                        if (qc == 0) {
                            int row = m0 + wm * 64 + mi * 16 + qr + h2 * 8;
                            psum[((size_t)z * 32 + chunk) * 1024 + row] = e;
                        }
                    }
                }
        }
    }
}

// ================== fully fused attention (ldmatrix fragments) ==================
__global__ void __launch_bounds__(256, 2) attn_fused(
    const __half* __restrict__ Qh, const __half* __restrict__ Kh,
    const __half* __restrict__ Vt, const float* __restrict__ psum,
    float* __restrict__ probs, __half* __restrict__ ctx)
{
    extern __shared__ __half hsm[];
    __half* qs = hsm;
    __half* kb = hsm + 128 * RS;
    __half* vb = hsm + 128 * RS + 2 * 64 * RS;
    __half* ph = hsm + 128 * RS + 4 * 64 * RS;
    float* rinv = (float*)(hsm + 2 * 128 * RS + 4 * 64 * RS);

    const unsigned su = smem_u32(hsm);
    const int tid = threadIdx.x;
    const int w = tid >> 5, lane = tid & 31;
    const int wm = w & 3, wn = w >> 2;            // 4 m x 2 n (32x32 tiles)
    const int qr = lane >> 2, qc = lane & 3;
    const int bh = blockIdx.y, b = bh >> 4, h = bh & 15;
    const int m0 = blockIdx.x * 128;
    float* prb = probs + ((size_t)bh << 20) + (size_t)m0 * 1024;
    const __half* qg = Qh + ((size_t)(b * 1024 + m0)) * 1024 + h * 64;
    const __half* kg = Kh + ((size_t)(b * 1024)) * 1024 + h * 64;
    const __half* vtb = Vt + ((size_t)bh << 16);  // [64][1024]

    {   // row sums from psum partials
        int row = tid >> 1, half = tid & 1;
        const float* pp = psum + ((size_t)bh * 32) * 1024 + m0 + row;
        float s = 0.0f;
        #pragma unroll
        for (int c = 0; c < 16; c++) s += pp[(half * 16 + c) * 1024];
        s += __shfl_xor_sync(0xffffffffu, s, 1);
        if (half == 0) rinv[row] = 1.0f / s;
    }

    // load Q tile [128][64]
    #pragma unroll
    for (int i = 0; i < 4; i++) {
        int idx = tid + i * 256;
        int r = idx >> 3, ch = idx & 7;
        cp16(&qs[r * RS + ch * 8], qg + (size_t)r * 1024 + ch * 8);
    }

    auto ldKV = [&](int kc) {
        __half* kd = kb + (kc & 1) * 64 * RS;
        __half* vd = vb + (kc & 1) * 64 * RS;
        #pragma unroll
        for (int i = 0; i < 2; i++) {
            int idx = tid + i * 256;
            int r = idx >> 3, ch = idx & 7;
            cp16(&kd[r * RS + ch * 8], kg + (size_t)(kc * 64 + r) * 1024 + ch * 8);
        }
        #pragma unroll
        for (int i = 0; i < 2; i++) {
            int idx = tid + i * 256;
            int r = idx >> 3, ch = idx & 7;
            cp16(&vd[r * RS + ch * 8], vtb + (size_t)r * 1024 + kc * 64 + ch * 8);
        }
    };

    // ldmatrix offsets (bytes)
    unsigned qoff[2], phoff[2], bo[2];
    {
        int arow = (lane & 15);
        int acol = (lane >> 4) << 3;
        #pragma unroll
        for (int mi = 0; mi < 2; mi++) {
            qoff[mi]  = ((wm * 32 + mi * 16 + arow) * RS + acol) * 2;
            phoff[mi] = qoff[mi] + (128 * RS + 4 * 64 * RS) * 2;
        }
        int brow = (lane & 7) + ((lane >> 4) << 3);
        int bcol = (lane & 8) ? 8 : 0;
        #pragma unroll
        for (int g = 0; g < 2; g++)
            bo[g] = ((wn * 32 + g * 16 + brow) * RS + bcol) * 2;
    }
    const unsigned kbase0 = su + (128 * RS) * 2;
    const unsigned vbase0 = su + (128 * RS + 2 * 64 * RS) * 2;

    float acc[2][4][4];
    #pragma unroll
    for (int mi = 0; mi < 2; mi++)
        #pragma unroll
        for (int ni = 0; ni < 4; ni++)
            #pragma unroll
            for (int j = 0; j < 4; j++) acc[mi][ni][j] = 0.0f;

    ldKV(0);
    CP_COMMIT();

    for (int kc = 0; kc < 16; kc++) {
        if (kc + 1 < 16) { ldKV(kc + 1); CP_COMMIT(); CP_WAIT1(); }
        else CP_WAIT0();
        __syncthreads();

        // ---- S chunk = Q @ K_chunk^T ----
        const unsigned kbase = kbase0 + (kc & 1) * (64 * RS) * 2;
        float sacc[2][4][4];
        #pragma unroll
        for (int mi = 0; mi < 2; mi++)
            #pragma unroll
            for (int ni = 0; ni < 4; ni++)
                #pragma unroll
                for (int j = 0; j < 4; j++) sacc[mi][ni][j] = 0.0f;
        #pragma unroll
        for (int k16 = 0; k16 < 4; k16++) {
            const unsigned kb2 = k16 * 32;
            unsigned ua[2][4], ub[2][4];
            #pragma unroll
            for (int mi = 0; mi < 2; mi++)
                ldm4(ua[mi], su + qoff[mi] + kb2);
            #pragma unroll
            for (int g = 0; g < 2; g++)
                ldm4(ub[g], kbase + bo[g] + kb2);
            #pragma unroll
            for (int mi = 0; mi < 2; mi++)
                #pragma unroll
                for (int ni = 0; ni < 4; ni++)
                    mma_f16(sacc[mi][ni], ua[mi], &ub[ni >> 1][(ni & 1) << 1]);
        }

        // ---- normalize: probs (f32) + P fp16 into ph ----
        #pragma unroll
        for (int mi = 0; mi < 2; mi++)
            #pragma unroll
            for (int ni = 0; ni < 4; ni++) {
                int col = wn * 32 + ni * 8 + (qc << 1);
                #pragma unroll
                for (int h2 = 0; h2 < 2; h2++) {
                    int r = wm * 32 + mi * 16 + qr + h2 * 8;
                    float inv = rinv[r];
                    float v0 = sacc[mi][ni][h2 * 2 + 0] * 0.125f;
                    float v1 = sacc[mi][ni][h2 * 2 + 1] * 0.125f;
                    float p0 = __expf(v0) * inv;
                    float p1 = __expf(v1) * inv;
                    *(float2*)&prb[(size_t)r * 1024 + kc * 64 + col] = make_float2(p0, p1);
                    *(unsigned*)&ph[r * RS + col] = packh(p0, p1);
                }
            }
        __syncthreads();

        // ---- AV: acc += P_chunk @ V_chunk^T ----
        const unsigned vbase = vbase0 + (kc & 1) * (64 * RS) * 2;
        #pragma unroll
        for (int k16 = 0; k16 < 4; k16++) {
            const unsigned kb2 = k16 * 32;
            unsigned ua[2][4], ub[2][4];
            #pragma unroll
            for (int mi = 0; mi < 2; mi++)
                ldm4(ua[mi], su + phoff[mi] + kb2);
            #pragma unroll
            for (int g = 0; g < 2; g++)
                ldm4(ub[g], vbase + bo[g] + kb2);
            #pragma unroll
            for (int mi = 0; mi < 2; mi++)
                #pragma unroll
                for (int ni = 0; ni < 4; ni++)
                    mma_f16(acc[mi][ni], ua[mi], &ub[ni >> 1][(ni & 1) << 1]);
        }
        __syncthreads();
    }

    // epilogue -> ctx fp16 (natural)
    #pragma unroll
    for (int mi = 0; mi < 2; mi++)
        #pragma unroll
        for (int ni = 0; ni < 4; ni++) {
            int c0 = h * 64 + wn * 32 + ni * 8 + (qc << 1);
            #pragma unroll
            for (int h2 = 0; h2 < 2; h2++) {
                int r = m0 + wm * 32 + mi * 16 + qr + h2 * 8;
                *(unsigned*)&ctx[((size_t)(b * 1024 + r)) * 1024 + c0] =
                    packh(acc[mi][ni][h2 * 2 + 0], acc[mi][ni][h2 * 2 + 1]);
            }
        }
}

// ---------------- prep: [S,B,D] -> batch-first fp16 ----------------
__global__ void prep_kernel(const float* __restrict__ src, const float* __restrict__ pos,
                            __half* __restrict__ qkin, __half* __restrict__ srcbf)
{
    size_t idx = (size_t)blockIdx.x * blockDim.x + threadIdx.x;
    if (idx >= (size_t)S_ * B_ * D_) return;
    int d = (int)(idx % D_);
    size_t sb = idx / D_;
    int b = (int)(sb % B_);
    int s = (int)(sb / B_);
    size_t o = ((size_t)(b * S_ + s)) * D_ + d;
    float sv = src[idx];
    qkin[o]  = __float2half(sv + pos[idx]);
    srcbf[o] = __float2half(sv);
}

// ---------------- merged weight transpose (all 6 weights, fp16) ------
__global__ void wprep(const float* __restrict__ Wq, const float* __restrict__ Wk,
                      const float* __restrict__ Wv, const float* __restrict__ Wo,
                      const float* __restrict__ W1, const float* __restrict__ W2,
                      __half* __restrict__ wr)
{
    __shared__ float t[32][33];
    int bid = blockIdx.x;
    const float* W; __half* Wt; int K, N, tt, nb;
    if (bid < 4096) {
        int w = bid >> 10; tt = bid & 1023; K = 1024; N = 1024; nb = 32;
        W = (w == 0) ? Wq : (w == 1) ? Wk : (w == 2) ? Wv : Wo;
        Wt = wr + (size_t)w * 1048576;
    } else if (bid < 8192) {
        tt = bid - 4096; K = 1024; N = 4096; nb = 128;
        W = W1; Wt = wr + 4194304;
    } else {
        tt = bid - 8192; K = 4096; N = 1024; nb = 32;
        W = W2; Wt = wr + 8388608;
    }
    int n0 = (tt % nb) * 32, k0 = (tt / nb) * 32;
    int tx = threadIdx.x, ty = threadIdx.y;
    #pragma unroll
    for (int i = 0; i < 32; i += 8)
        t[ty + i][tx] = W[(size_t)(k0 + ty + i) * N + n0 + tx];
    __syncthreads();
    #pragma unroll
    for (int i = 0; i < 32; i += 8) {
        int n = ty + i;
        Wt[(size_t)(n0 + n) * K + k0 + tx] = __float2half(t[tx][n]);
    }
}

// ---------------- fused add + LayerNorm (+ optional fp16 copy) -------
__global__ void ln_kernel(const float* __restrict__ in1, int in1_sbd,
                          const float* __restrict__ in2,
                          const float* __restrict__ gamma, const float* __restrict__ beta,
                          float* __restrict__ out, int out_sbd,
                          __half* __restrict__ xp)
{
    int m = blockIdx.x;
    int b = m / S_, s = m % S_;
    size_t sbd_off = ((size_t)(s * B_ + b)) * D_;
    size_t bf_off  = (size_t)m * D_;
    const float* p1 = in1 + (in1_sbd ? sbd_off : bf_off);
    const float* p2 = in2 + bf_off;
    float* po = out + (out_sbd ? sbd_off : bf_off);

    __shared__ float xs[D_];
    __shared__ float r1[256], r2[256];
    int tid = threadIdx.x;
    float s1 = 0.0f, s2 = 0.0f;
    for (int d = tid; d < D_; d += 256) {
        float v = p1[d] + p2[d];
        xs[d] = v; s1 += v; s2 += v * v;
    }
    r1[tid] = s1; r2[tid] = s2;
    __syncthreads();
    for (int st = 128; st > 0; st >>= 1) {
        if (tid < st) { r1[tid] += r1[tid + st]; r2[tid] += r2[tid + st]; }
        __syncthreads();
    }
    float mean = r1[0] * (1.0f / D_);
    float var  = r2[0] * (1.0f / D_) - mean * mean;
    float rstd = rsqrtf(var + 1e-5f);
    for (int d = tid; d < D_; d += 256) {
        float v = (xs[d] - mean) * rstd * gamma[d] + beta[d];
        po[d] = v;
        if (xp) xp[bf_off + d] = __float2half(v);
    }
}

// ---------------- launch ----------------
extern "C" void kernel_launch(void* const* d_in, const int* in_sizes, int n_in,
                              void* d_out, int out_size)
{
    static __half *qkin = nullptr, *srcbf, *Qh, *Kh, *vt, *ctxh, *h1, *wr;
    static float *ao, *x, *f2, *psum, *attn_fb;
    if (!qkin) {
        cudaGetSymbolAddress((void**)&qkin,  g_qkin);
        cudaGetSymbolAddress((void**)&srcbf, g_srcbf);
        cudaGetSymbolAddress((void**)&Qh,    g_Q);
        cudaGetSymbolAddress((void**)&Kh,    g_K);
        cudaGetSymbolAddress((void**)&vt,    g_vt);
        cudaGetSymbolAddress((void**)&ctxh,  g_ctx);
        cudaGetSymbolAddress((void**)&h1,    g_h1);
        cudaGetSymbolAddress((void**)&wr,    g_wr);
        cudaGetSymbolAddress((void**)&ao,    g_ao);
        cudaGetSymbolAddress((void**)&x,     g_x);
        cudaGetSymbolAddress((void**)&f2,    g_f2);
        cudaGetSymbolAddress((void**)&psum,  g_psum);
        cudaGetSymbolAddress((void**)&attn_fb, g_attn_fb);
    }

    const float* src = (const float*)d_in[0];
    const float* pos = (const float*)d_in[1];
    const float* Wq  = (const float*)d_in[2];
    const float* bq  = (const float*)d_in[3];
    const float* Wk  = (const float*)d_in[4];
    const float* bk  = (const float*)d_in[5];
    const float* Wv  = (const float*)d_in[6];
    const float* bv  = (const float*)d_in[7];
    const float* Wo  = (const float*)d_in[8];
    const float* bo  = (const float*)d_in[9];
    const float* W1  = (const float*)d_in[10];
    const float* b1  = (const float*)d_in[11];
    const float* W2  = (const float*)d_in[12];
    const float* b2  = (const float*)d_in[13];
    const float* g1  = (const float*)d_in[14];
    const float* be1 = (const float*)d_in[15];
    const float* g2  = (const float*)d_in[16];
    const float* be2 = (const float*)d_in[17];

    float* out = (float*)d_out;
    long long need = (long long)S_ * B_ * D_ + (long long)B_ * H_ * S_ * S_;
    float* probs  = ((long long)out_size >= need) ? out + (size_t)S_ * B_ * D_ : attn_fb;

    const int SMT = 2 * (2 * 128 * RS) * 2;               // 73728 B
    const int SMA = (2 * 128 * RS + 4 * 64 * RS) * 2 + 512; // 74240 B
    cudaFuncSetAttribute(tgemm,      cudaFuncAttributeMaxDynamicSharedMemorySize, SMT);
    cudaFuncSetAttribute(attn_fused, cudaFuncAttributeMaxDynamicSharedMemorySize, SMA);

    __half* wqr = wr;
    __half* wkr = wr + 1048576;
    __half* wvr = wr + 2097152;
    __half* wor = wr + 3145728;
    __half* w1r = wr + 4194304;
    __half* w2r = wr + 8388608;

    // 1) prep
    wprep<<<12288, dim3(32, 8)>>>(Wq, Wk, Wv, Wo, W1, W2, wr);
    prep_kernel<<<32768, 256>>>(src, pos, qkin, srcbf);

    const long long SD = (long long)S_ * D_;
    const long long SS = (long long)S_ * S_;

    // 2-4) QKV projections: Q,K fp16; V -> transposed fp16 Vt
    tgemm<<<dim3(8, 64, 1), 128, SMT>>>(qkin, wqr, bq, nullptr, Qh, nullptr,
        1024, D_, D_, D_, 1, 0, 0, 0, 0, 0, 0, 1.0f, 0, 1);
    tgemm<<<dim3(8, 64, 1), 128, SMT>>>(qkin, wkr, bk, nullptr, Kh, nullptr,
        1024, D_, D_, D_, 1, 0, 0, 0, 0, 0, 0, 1.0f, 0, 1);
    tgemm<<<dim3(8, 64, 1), 128, SMT>>>(srcbf, wvr, bv, nullptr, vt, nullptr,
        1024, D_, D_, D_, 1, 0, 0, 0, 0, 0, 0, 1.0f, 0, 2);

    // 5) psum pass: only exp row-sum partials stored
    tgemm<<<dim3(8, 8, B_ * H_), 128, SMT>>>(Qh, Kh, nullptr, nullptr, nullptr, psum,
        64, D_, D_, S_, H_,
        SD, 64, SD, 64, (long long)H_ * SS, SS, 0.125f, 0, 0);

    // 6) fused attention
    attn_fused<<<dim3(8, B_ * H_), 256, SMA>>>(Qh, Kh, vt, psum, probs, ctxh);

    // 7) output projection (f32 out)
    tgemm<<<dim3(8, 64, 1), 128, SMT>>>(ctxh, wor, bo, ao, nullptr, nullptr,
        1024, D_, D_, D_, 1, 0, 0, 0, 0, 0, 0, 1.0f, 0, 0);

    // 8) LN1: x f32 + xp fp16 (reuse Qh)
    __half* xp = Qh;
    ln_kernel<<<M_TOK, 256>>>(src, 1, ao, g1, be1, x, 0, xp);

    // 9-10) FFN
    tgemm<<<dim3(32, 64, 1), 128, SMT>>>(xp, w1r, b1, nullptr, h1, nullptr,
        1024, D_, D_, F_, 1, 0, 0, 0, 0, 0, 0, 1.0f, 1, 1);
    tgemm<<<dim3(8, 64, 1), 128, SMT>>>(h1, w2r, b2, f2, nullptr, nullptr,
        4096, F_, F_, D_, 1, 0, 0, 0, 0, 0, 0, 1.0f, 0, 0);

    // 11) LN2 -> out
    ln_kernel<<<M_TOK, 256>>>(x, 0, f2, g2, be2, out, 1, nullptr);
}